// round 7
// baseline (speedup 1.0000x reference)
#include <cuda_runtime.h>
#include <cuda_bf16.h>
#include <math.h>
#include <cstdint>

// tcgen05 is only legal on arch-specific targets (sm_103a / sm_100a).
// The harness's nvcc also runs a generic compute_103 PTX pass; guard so that
// pass compiles empty bodies (the sm_103a cubin is what actually runs).
#if !defined(__CUDA_ARCH__) || defined(__CUDA_ARCH_FEAT_SM103_ALL) || \
    defined(__CUDA_ARCH_FEAT_SM100_ALL) || defined(__CUDA_ARCH_FEAT_SM101_ALL)
#define HAS_TCGEN05 1
#else
#define HAS_TCGEN05 0
#endif

// Problem dims
#define Bb   128
#define Tt   128
#define Cc   256
#define Hh   4
#define HS   64
#define Ll   6
#define DFF  1024
#define Vv   10000
#define BT   (Bb*Tt)   // 16384
#define VPAD 10240     // 80*128 (LM head padded to 4-tile groups)
#define QKVN 768

// ================= PTX helpers (sm_103a tcgen05) ===========================
__device__ __forceinline__ uint32_t smem_to_u32(const void* p) {
    uint32_t a;
    asm("{ .reg .u64 t; cvta.to.shared.u64 t, %1; cvt.u32.u64 %0, t; }"
        : "=r"(a) : "l"(p));
    return a;
}

#if HAS_TCGEN05
__device__ __forceinline__ uint32_t elect_one_pred() {
    uint32_t pred;
    asm volatile(
        "{\n\t.reg .pred p;\n\telect.sync _|p, 0xFFFFFFFF;\n\t"
        "selp.b32 %0, 1, 0, p;\n\t}"
        : "=r"(pred));
    return pred;
}
#define TCGEN05_ALLOC(smem_addr, nCols) \
    asm volatile("tcgen05.alloc.cta_group::1.sync.aligned.shared::cta.b32 [%0], %1;" \
        :: "r"((uint32_t)(smem_addr)), "r"((uint32_t)(nCols)) : "memory")
#define TCGEN05_DEALLOC(tmem_addr, nCols) \
    asm volatile("tcgen05.dealloc.cta_group::1.sync.aligned.b32 %0, %1;" \
        :: "r"(tmem_addr), "r"((uint32_t)(nCols)))
#define TCGEN05_RELINQ() \
    asm volatile("tcgen05.relinquish_alloc_permit.cta_group::1.sync.aligned;")
#define TCGEN05_COMMIT(mbar) \
    asm volatile("tcgen05.commit.cta_group::1.mbarrier::arrive::one.shared::cluster.b64 [%0];" \
        :: "r"((uint32_t)(mbar)) : "memory")
#define TCGEN05_FENCE_BEFORE() \
    asm volatile("tcgen05.fence::before_thread_sync;" ::: "memory")
#define TCGEN05_FENCE_AFTER() \
    asm volatile("tcgen05.fence::after_thread_sync;" ::: "memory")
#define TCGEN05_WAIT_LD() \
    asm volatile("tcgen05.wait::ld.sync.aligned;" ::: "memory")
#define FENCE_PROXY_ASYNC_SHARED_CTA() \
    asm volatile("fence.proxy.async.shared::cta;" ::: "memory")
#define MBARRIER_INIT(mbar, count) \
    asm volatile("mbarrier.init.shared.b64 [%0], %1;" \
        :: "r"((uint32_t)(mbar)), "r"((uint32_t)(count)) : "memory")
#define MBARRIER_INVAL(mbar) \
    asm volatile("mbarrier.inval.shared.b64 [%0];" :: "r"((uint32_t)(mbar)) : "memory")
// Non-blocking poll: mbarrier.test_wait in a spin loop, no sleep.
#define MBARRIER_POLL(mbar, parity) do { \
    uint32_t _mbar = (uint32_t)(mbar); \
    uint32_t _par  = (uint32_t)(parity); \
    uint32_t _done = 0; \
    while (!_done) { \
        asm volatile( \
            "{\n\t.reg .pred p;\n\t" \
            "mbarrier.test_wait.parity.acquire.cta.shared::cta.b64 p, [%1], %2;\n\t" \
            "selp.b32 %0, 1, 0, p;\n\t}" \
            : "=r"(_done) : "r"(_mbar), "r"(_par) : "memory"); \
    } \
} while (0)
// Async 16B copy global->shared (LDGSTS). Register-free, deep MLP.
__device__ __forceinline__ void cp_async16(uint32_t dst, const void* src) {
    asm volatile("cp.async.cg.shared.global [%0], [%1], 16;"
        :: "r"(dst), "l"(src) : "memory");
}
#define CP_ASYNC_COMMIT() asm volatile("cp.async.commit_group;" ::: "memory")
#define CP_ASYNC_WAIT0()  asm volatile("cp.async.wait_group 0;" ::: "memory")
#define TCGEN05_LD_32X32B_X32(r, tmem_addr) \
    asm volatile( \
        "tcgen05.ld.sync.aligned.32x32b.x32.b32 " \
        "{%0, %1, %2, %3, %4, %5, %6, %7, " \
        " %8, %9, %10, %11, %12, %13, %14, %15, " \
        " %16, %17, %18, %19, %20, %21, %22, %23, " \
        " %24, %25, %26, %27, %28, %29, %30, %31}, [%32];" \
        : "=r"((r)[0]),  "=r"((r)[1]),  "=r"((r)[2]),  "=r"((r)[3]), \
          "=r"((r)[4]),  "=r"((r)[5]),  "=r"((r)[6]),  "=r"((r)[7]), \
          "=r"((r)[8]),  "=r"((r)[9]),  "=r"((r)[10]), "=r"((r)[11]), \
          "=r"((r)[12]), "=r"((r)[13]), "=r"((r)[14]), "=r"((r)[15]), \
          "=r"((r)[16]), "=r"((r)[17]), "=r"((r)[18]), "=r"((r)[19]), \
          "=r"((r)[20]), "=r"((r)[21]), "=r"((r)[22]), "=r"((r)[23]), \
          "=r"((r)[24]), "=r"((r)[25]), "=r"((r)[26]), "=r"((r)[27]), \
          "=r"((r)[28]), "=r"((r)[29]), "=r"((r)[30]), "=r"((r)[31]) \
        : "r"(tmem_addr))

// cg1 bf16 SS MMA (A in SMEM, B in SMEM), fp32 accumulate
__device__ __forceinline__ void mma_bf16_ss(uint32_t d, uint64_t a, uint64_t b,
                                            uint32_t idesc, bool en) {
    uint32_t e = en ? 1u : 0u;
    asm volatile(
        "{\n\t.reg .pred p;\n\t"
        "setp.ne.u32 p, %5, 0;\n\t"
        "tcgen05.mma.cta_group::1.kind::f16 [%0], %1, %2, %3, {%4, %4, %4, %4}, p;\n\t}"
        :: "r"(d), "l"(a), "l"(b), "r"(idesc), "r"(0u), "r"(e)
        : "memory");
}
#endif  // HAS_TCGEN05

// 64-bit SMEM descriptor: SW128, Blackwell v1, LBO=1, SBO=64 (K-major 128B rows)
static __device__ __forceinline__ uint64_t make_desc_sw128(uint32_t addr) {
    const uint64_t base =
        (uint64_t(2)  << 61) | (uint64_t(1) << 46) |
        (uint64_t(64) << 32) | (uint64_t(1) << 16);
    return base | ((uint64_t)(addr >> 4) & 0x3FFF);
}
#define SW128(bo) ((bo) ^ (((bo) >> 3) & 0x70))

// ================= scratch (device globals) ================================
__device__ __align__(16) float g_x  [BT*Cc];
__device__ __align__(16) float g_qkv[BT*QKVN];
// bf16 hi/lo activations
__device__ __align__(16) __nv_bfloat16 g_hh[BT*Cc],  g_hl[BT*Cc];
__device__ __align__(16) __nv_bfloat16 g_ah[BT*Cc],  g_al[BT*Cc];
__device__ __align__(16) __nv_bfloat16 g_fh[BT*DFF], g_fl[BT*DFF];
// transposed+split weights: [N(pad), K] K-major
__device__ __align__(16) __nv_bfloat16 g_qkvT_h[Ll*QKVN*Cc], g_qkvT_l[Ll*QKVN*Cc];
__device__ __align__(16) __nv_bfloat16 g_pT_h [Ll*Cc*Cc],    g_pT_l [Ll*Cc*Cc];
__device__ __align__(16) __nv_bfloat16 g_w1T_h[Ll*DFF*Cc],   g_w1T_l[Ll*DFF*Cc];
__device__ __align__(16) __nv_bfloat16 g_w2T_h[Ll*Cc*DFF],   g_w2T_l[Ll*Cc*DFF];
__device__ __align__(16) __nv_bfloat16 g_lmT_h[VPAD*Cc],     g_lmT_l[VPAD*Cc];

// ================= small kernels ===========================================
__global__ void embed_kernel(const int* __restrict__ idx,
                             const float* __restrict__ tok,
                             const float* __restrict__ pos,
                             float* __restrict__ x) {
    int i = blockIdx.x * blockDim.x + threadIdx.x;
    const int total = BT * Cc;
    for (; i < total; i += gridDim.x * blockDim.x) {
        int row = i >> 8;
        int c   = i & 255;
        int t   = row & (Tt - 1);
        x[i] = tok[idx[row] * Cc + c] + pos[t * Cc + c];
    }
}

// generic: W [K,N] fp32 (layer-strided) -> out [Npad,K] bf16 hi/lo
__global__ void transpose_split_g(const float* __restrict__ W,
                                  __nv_bfloat16* __restrict__ oh,
                                  __nv_bfloat16* __restrict__ ol,
                                  int K, int N,
                                  size_t wstride, size_t ostride) {
    __shared__ float t[32][33];
    int l  = blockIdx.z;
    W  += (size_t)l * wstride;
    oh += (size_t)l * ostride;
    ol += (size_t)l * ostride;
    int n0 = blockIdx.x * 32, k0 = blockIdx.y * 32;
    int tx = threadIdx.x, ty = threadIdx.y;
    #pragma unroll
    for (int i = 0; i < 4; i++) {
        int k = k0 + ty + i * 8;
        int n = n0 + tx;
        t[ty + i * 8][tx] = (n < N) ? W[(size_t)k * N + n] : 0.f;
    }
    __syncthreads();
    #pragma unroll
    for (int i = 0; i < 4; i++) {
        int n = n0 + ty + i * 8;
        int k = k0 + tx;
        float v = t[tx][ty + i * 8];
        __nv_bfloat16 hi = __float2bfloat16(v);
        oh[(size_t)n * K + k] = hi;
        ol[(size_t)n * K + k] = __float2bfloat16(v - __bfloat162float(hi));
    }
}

// fused QKV transpose: wq/wk/wv [L][256][256] -> out [L][768][256]
__global__ void qkv_transpose(const float* __restrict__ wq,
                              const float* __restrict__ wk,
                              const float* __restrict__ wv,
                              __nv_bfloat16* __restrict__ oh,
                              __nv_bfloat16* __restrict__ ol) {
    __shared__ float t[32][33];
    int l  = blockIdx.z;
    int n0 = blockIdx.x * 32, k0 = blockIdx.y * 32;
    const float* W;
    int nb;
    if      (n0 < 256) { W = wq + (size_t)l * Cc * Cc; nb = n0; }
    else if (n0 < 512) { W = wk + (size_t)l * Cc * Cc; nb = n0 - 256; }
    else               { W = wv + (size_t)l * Cc * Cc; nb = n0 - 512; }
    oh += (size_t)l * QKVN * Cc;
    ol += (size_t)l * QKVN * Cc;
    int tx = threadIdx.x, ty = threadIdx.y;
    #pragma unroll
    for (int i = 0; i < 4; i++) {
        int k = k0 + ty + i * 8;
        t[ty + i * 8][tx] = W[(size_t)k * Cc + nb + tx];
    }
    __syncthreads();
    #pragma unroll
    for (int i = 0; i < 4; i++) {
        int n = n0 + ty + i * 8;
        int k = k0 + tx;
        float v = t[tx][ty + i * 8];
        __nv_bfloat16 hi = __float2bfloat16(v);
        oh[(size_t)n * Cc + k] = hi;
        ol[(size_t)n * Cc + k] = __float2bfloat16(v - __bfloat162float(hi));
    }
}

// LayerNorm, outputs bf16 hi/lo split
__global__ void ln_split_kernel(const float* __restrict__ x,
                                const float* __restrict__ g,
                                const float* __restrict__ b,
                                __nv_bfloat16* __restrict__ oh,
                                __nv_bfloat16* __restrict__ ol) {
    int row = blockIdx.x;
    int tid = threadIdx.x;
    float v = x[row * Cc + tid];
    float s = v, s2 = v * v;
    #pragma unroll
    for (int off = 16; off > 0; off >>= 1) {
        s  += __shfl_xor_sync(0xffffffffu, s,  off);
        s2 += __shfl_xor_sync(0xffffffffu, s2, off);
    }
    __shared__ float ss[8], ss2[8];
    __shared__ float mean_s, rstd_s;
    int w = tid >> 5, l = tid & 31;
    if (l == 0) { ss[w] = s; ss2[w] = s2; }
    __syncthreads();
    if (tid == 0) {
        float S = 0.f, S2 = 0.f;
        #pragma unroll
        for (int i = 0; i < 8; i++) { S += ss[i]; S2 += ss2[i]; }
        float m   = S * (1.0f / Cc);
        float var = S2 * (1.0f / Cc) - m * m;
        mean_s = m;
        rstd_s = rsqrtf(var + 1e-5f);
    }
    __syncthreads();
    float y = (v - mean_s) * rstd_s * g[tid] + b[tid];
    __nv_bfloat16 hi = __float2bfloat16(y);
    oh[row * Cc + tid] = hi;
    ol[row * Cc + tid] = __float2bfloat16(y - __bfloat162float(hi));
}

// ================= tcgen05 GEMM (single buffer, cp.async loads) =============
// C[M,N] = (Ah+Al)[M,K] @ (Bh+Bl)^T  with B stored [Npad,K] K-major.
// tile 128x128, K-chunk 64 (one SW128 atom row of 128B).
// Loads use cp.async (LDGSTS): all 16 per thread in flight at once — the
// R6 LDG->STS chains had MLP~1 and paid serialized L2 latency (~25k cy/chunk).
#define GSM_TPTR 0
#define GSM_MBAR 8
#define GSM_AH   1024
#define GSM_AL   (1024 + 16384)
#define GSM_BH   (1024 + 32768)
#define GSM_BL   (1024 + 49152)
#define GSM_SIZE (1024 + 65536)
#define GEMM_IDESC 0x8200490u   // f32 acc, bf16 a/b, N=128, M=128

template<bool BIAS, bool RELU, bool RESID, bool SPLIT>
__global__ __launch_bounds__(256)
void tc_gemm(const __nv_bfloat16* __restrict__ Ah, const __nv_bfloat16* __restrict__ Al,
             const __nv_bfloat16* __restrict__ Bh, const __nv_bfloat16* __restrict__ Bl,
             const float* __restrict__ bias, const float* __restrict__ res,
             float* __restrict__ outf,
             __nv_bfloat16* __restrict__ oh, __nv_bfloat16* __restrict__ ol,
             int Nstore, int K, int ntiles, int Npad) {
#if HAS_TCGEN05
    extern __shared__ char smem[];
    const uint32_t smem_base = smem_to_u32(smem);
    const int tid  = threadIdx.x;
    const int wid  = tid >> 5;
    const int lane = tid & 31;
    const int bm   = blockIdx.y * 128;
    const int bn0  = blockIdx.x * 128 * ntiles;

    if (wid == 0) {
        TCGEN05_ALLOC(smem_base + GSM_TPTR, 128);
        TCGEN05_RELINQ();
    }
    if (tid == 0) MBARRIER_INIT(smem_base + GSM_MBAR, 1);
    __syncthreads();
    uint32_t tmem;
    asm volatile("ld.shared.b32 %0, [%1];" : "=r"(tmem) : "r"(smem_base + GSM_TPTR));

    const uint64_t dAh = make_desc_sw128(smem_base + GSM_AH);
    const uint64_t dAl = make_desc_sw128(smem_base + GSM_AL);
    const uint64_t dBh = make_desc_sw128(smem_base + GSM_BH);
    const uint64_t dBl = make_desc_sw128(smem_base + GSM_BL);

    // per-thread load mapping: 4 iters x one 16B vector per tile buffer
    const int lr = tid >> 3;            // row base 0..31 (+32*i)
    const int lb = (tid & 7) * 16;      // byte offset in 128B row

    const int nchunks = K >> 6;   // K/64
    int cc = 0;                   // global chunk counter (mbarrier parity)

    for (int t = 0; t < ntiles; t++) {
        const int bn = bn0 + t * 128;
        if (bn >= Npad) break;

        for (int c = 0; c < nchunks; c++) {
            const int k0 = c << 6;
            #pragma unroll
            for (int i = 0; i < 4; i++) {
                int r = lr + i * 32;
                uint32_t so = SW128(r * 128 + lb);
                const char* sa = (const char*)(Ah + (size_t)(bm + r) * K + k0) + lb;
                const char* sb = (const char*)(Al + (size_t)(bm + r) * K + k0) + lb;
                const char* sc = (const char*)(Bh + (size_t)(bn + r) * K + k0) + lb;
                const char* sd = (const char*)(Bl + (size_t)(bn + r) * K + k0) + lb;
                cp_async16(smem_base + GSM_AH + so, sa);
                cp_async16(smem_base + GSM_AL + so, sb);
                cp_async16(smem_base + GSM_BH + so, sc);
                cp_async16(smem_base + GSM_BL + so, sd);
            }
            CP_ASYNC_COMMIT();
            CP_ASYNC_WAIT0();
            FENCE_PROXY_ASYNC_SHARED_CTA();
            __syncthreads();

            if (wid == 0 && elect_one_pred()) {
                #pragma unroll
                for (int ks = 0; ks < 4; ks++) {
                    uint64_t oa = (uint64_t)(ks * 2);
                    mma_bf16_ss(tmem, dAh + oa, dBh + oa, GEMM_IDESC, !(c == 0 && ks == 0));
                    mma_bf16_ss(tmem, dAh + oa, dBl + oa, GEMM_IDESC, true);
                    mma_bf16_ss(tmem, dAl + oa, dBh + oa, GEMM_IDESC, true);
                }
                TCGEN05_COMMIT(smem_base + GSM_MBAR);
            }
            // warp 0 polls (no sleep), everyone else joins at the barrier
            if (wid == 0) MBARRIER_POLL(smem_base + GSM_MBAR, cc & 1);
            __syncthreads();
            cc++;
        }
        TCGEN05_FENCE_AFTER();

        // epilogue: warps 0-3 cols 0-63, warps 4-7 cols 64-127
        const int wp   = wid & 3;
        const int colg = (wid >> 2) * 64;
        const int m    = bm + wp * 32 + lane;
        #pragma unroll
        for (int half = 0; half < 2; half++) {
            int cb = colg + half * 32;
            uint32_t r[32];
            TCGEN05_LD_32X32B_X32(r, tmem + cb);
            TCGEN05_WAIT_LD();
            #pragma unroll
            for (int j = 0; j < 32; j++) {
                int n = bn + cb + j;
                if (n < Nstore) {
                    float val = __uint_as_float(r[j]);
                    if (BIAS)  val += bias[n];
                    if (RELU)  val = fmaxf(val, 0.f);
                    size_t idx = (size_t)m * Nstore + n;
                    if (RESID) val += res[idx];
                    if (SPLIT) {
                        __nv_bfloat16 hi = __float2bfloat16(val);
                        oh[idx] = hi;
                        ol[idx] = __float2bfloat16(val - __bfloat162float(hi));
                    } else {
                        outf[idx] = val;
                    }
                }
            }
        }
        TCGEN05_FENCE_BEFORE();
        __syncthreads();   // TMEM reads done in all warps before next tile's MMAs
    }

    if (tid == 0) MBARRIER_INVAL(smem_base + GSM_MBAR);
    __syncthreads();
    if (wid == 0) TCGEN05_DEALLOC(tmem, 128);
#endif  // HAS_TCGEN05
}

// ================= fused causal attention (fused qkv in, bf16 hi/lo out) ----
#define ATTN_SMEM ((64*128 + 128*68 + 4*64) * 4)

__global__ __launch_bounds__(128)
void attn_kernel(const float* __restrict__ qkv,
                 __nv_bfloat16* __restrict__ oh, __nv_bfloat16* __restrict__ ol) {
    extern __shared__ float sm[];
    float* Kst = sm;                       // [64][128]
    float* Vs  = sm + 64 * 128;            // [128][68]
    float* qs  = sm + 64 * 128 + 128 * 68; // [4][64]

    const int b    = blockIdx.x >> 2;
    const int h    = blockIdx.x & 3;
    const int tid  = threadIdx.x;
    const int lane = tid & 31;
    const int w    = tid >> 5;

    const float* base_bt = qkv + (size_t)(b * Tt) * QKVN + h * HS;
    {
        const float* krow = base_bt + 256 + (size_t)tid * QKVN;
        const float* vrow = base_bt + 512 + (size_t)tid * QKVN;
        #pragma unroll
        for (int d4 = 0; d4 < 16; d4++) {
            float4 kv = *(const float4*)(krow + d4 * 4);
            Kst[(d4 * 4 + 0) * 128 + tid] = kv.x;
            Kst[(d4 * 4 + 1) * 128 + tid] = kv.y;
            Kst[(d4 * 4 + 2) * 128 + tid] = kv.z;
            Kst[(d4 * 4 + 3) * 128 + tid] = kv.w;
            *(float4*)&Vs[tid * 68 + d4 * 4] = *(const float4*)(vrow + d4 * 4);
        }
    }
    __syncthreads();

    const float scale = 0.0625f;  // 256^-0.5

    for (int r = 0; r < 32; r++) {
        const int qr = r * 4 + w;
        const float* qrow = base_bt + (size_t)qr * QKVN;
        qs[w * 64 + lane]      = qrow[lane];
        qs[w * 64 + lane + 32] = qrow[lane + 32];
        __syncwarp();

        float s0 = 0.f, s1 = 0.f, s2 = 0.f, s3 = 0.f;
        #pragma unroll 8
        for (int d = 0; d < 64; d++) {
            float qd = qs[w * 64 + d];
            const float* kd = &Kst[d * 128];
            s0 = fmaf(qd, kd[lane],      s0);
            s1 = fmaf(qd, kd[lane + 32], s1);
            s2 = fmaf(qd, kd[lane + 64], s2);
            s3 = fmaf(qd, kd[lane + 96], s3);
        }
        s0 *= scale; s1 *= scale; s2 *= scale; s3 *= scale;

        const int k0 = lane, k1 = lane + 32, k2 = lane + 64, k3 = lane + 96;
        float mx = -1e30f;
        if (k0 <= qr) mx = fmaxf(mx, s0);
        if (k1 <= qr) mx = fmaxf(mx, s1);
        if (k2 <= qr) mx = fmaxf(mx, s2);
        if (k3 <= qr) mx = fmaxf(mx, s3);
        #pragma unroll
        for (int off = 16; off > 0; off >>= 1)
            mx = fmaxf(mx, __shfl_xor_sync(0xffffffffu, mx, off));

        float e0 = (k0 <= qr) ? __expf(s0 - mx) : 0.f;
        float e1 = (k1 <= qr) ? __expf(s1 - mx) : 0.f;
        float e2 = (k2 <= qr) ? __expf(s2 - mx) : 0.f;
        float e3 = (k3 <= qr) ? __expf(s3 - mx) : 0.f;

        float sum = e0 + e1 + e2 + e3;
        #pragma unroll
        for (int off = 16; off > 0; off >>= 1)
            sum += __shfl_xor_sync(0xffffffffu, sum, off);
        float rs = 1.0f / sum;
        float p0 = e0 * rs, p1 = e1 * rs, p2 = e2 * rs, p3 = e3 * rs;

        float o0 = 0.f, o1 = 0.f;
        for (int kk = 0; kk <= qr; kk++) {
            float psel = (kk < 32) ? p0 : (kk < 64) ? p1 : (kk < 96) ? p2 : p3;
            float pk = __shfl_sync(0xffffffffu, psel, kk & 31);
            const float* vrow = &Vs[kk * 68];
            o0 = fmaf(pk, vrow[lane],      o0);
            o1 = fmaf(pk, vrow[lane + 32], o1);
        }

        size_t obase = (size_t)(b * Tt + qr) * Cc + h * HS;
        __nv_bfloat16 h0 = __float2bfloat16(o0);
        __nv_bfloat16 h1 = __float2bfloat16(o1);
        oh[obase + lane]      = h0;
        oh[obase + lane + 32] = h1;
        ol[obase + lane]      = __float2bfloat16(o0 - __bfloat162float(h0));
        ol[obase + lane + 32] = __float2bfloat16(o1 - __bfloat162float(h1));
        __syncwarp();
    }
}

// ================= launch ===================================================
extern "C" void kernel_launch(void* const* d_in, const int* in_sizes, int n_in,
                              void* d_out, int out_size) {
    const int*   idx   = (const int*)  d_in[0];
    const float* tok   = (const float*)d_in[1];
    const float* pos   = (const float*)d_in[2];
    const float* ln1g  = (const float*)d_in[3];
    const float* ln1b  = (const float*)d_in[4];
    const float* wq    = (const float*)d_in[5];
    const float* wk    = (const float*)d_in[6];
    const float* wv    = (const float*)d_in[7];
    const float* projw = (const float*)d_in[8];
    const float* projb = (const float*)d_in[9];
    const float* ln2g  = (const float*)d_in[10];
    const float* ln2b  = (const float*)d_in[11];
    const float* w1    = (const float*)d_in[12];
    const float* b1    = (const float*)d_in[13];
    const float* w2    = (const float*)d_in[14];
    const float* b2    = (const float*)d_in[15];
    const float* lnfg  = (const float*)d_in[16];
    const float* lnfb  = (const float*)d_in[17];
    const float* lmw   = (const float*)d_in[18];
    const float* lmb   = (const float*)d_in[19];
    float* out = (float*)d_out;

    float *x, *qkv;
    __nv_bfloat16 *hh, *hl, *ah, *al, *fh, *fl;
    __nv_bfloat16 *qkvTh, *qkvTl, *pTh, *pTl;
    __nv_bfloat16 *w1Th, *w1Tl, *w2Th, *w2Tl, *lmTh, *lmTl;
    cudaGetSymbolAddress((void**)&x,   g_x);
    cudaGetSymbolAddress((void**)&qkv, g_qkv);
    cudaGetSymbolAddress((void**)&hh, g_hh);  cudaGetSymbolAddress((void**)&hl, g_hl);
    cudaGetSymbolAddress((void**)&ah, g_ah);  cudaGetSymbolAddress((void**)&al, g_al);
    cudaGetSymbolAddress((void**)&fh, g_fh);  cudaGetSymbolAddress((void**)&fl, g_fl);
    cudaGetSymbolAddress((void**)&qkvTh, g_qkvT_h); cudaGetSymbolAddress((void**)&qkvTl, g_qkvT_l);
    cudaGetSymbolAddress((void**)&pTh,  g_pT_h);    cudaGetSymbolAddress((void**)&pTl,  g_pT_l);
    cudaGetSymbolAddress((void**)&w1Th, g_w1T_h);   cudaGetSymbolAddress((void**)&w1Tl, g_w1T_l);
    cudaGetSymbolAddress((void**)&w2Th, g_w2T_h);   cudaGetSymbolAddress((void**)&w2Tl, g_w2T_l);
    cudaGetSymbolAddress((void**)&lmTh, g_lmT_h);   cudaGetSymbolAddress((void**)&lmTl, g_lmT_l);

    cudaFuncSetAttribute(attn_kernel,
                         cudaFuncAttributeMaxDynamicSharedMemorySize, ATTN_SMEM);
    cudaFuncSetAttribute(tc_gemm<false,false,false,false>,
                         cudaFuncAttributeMaxDynamicSharedMemorySize, GSM_SIZE);
    cudaFuncSetAttribute(tc_gemm<true,false,true,false>,
                         cudaFuncAttributeMaxDynamicSharedMemorySize, GSM_SIZE);
    cudaFuncSetAttribute(tc_gemm<true,true,false,true>,
                         cudaFuncAttributeMaxDynamicSharedMemorySize, GSM_SIZE);
    cudaFuncSetAttribute(tc_gemm<true,false,false,false>,
                         cudaFuncAttributeMaxDynamicSharedMemorySize, GSM_SIZE);

    dim3 tb(32, 8);
    const dim3 gC(Cc / 128,   BT / 128);   // N=256
    const dim3 gQ(QKVN / 128, BT / 128);   // N=768
    const dim3 gF(DFF / 128,  BT / 128);   // N=1024
    const dim3 gV(VPAD / 512, BT / 128);   // LM head: 20 x 128, 4 N-tiles/CTA

    // Launch order: index 3 is the profiled launch (ncu lands on our #3).
    embed_kernel<<<2048, 256>>>(idx, tok, pos, x);                                  // 0
    qkv_transpose<<<dim3(QKVN/32, Cc/32, Ll), tb>>>(wq, wk, wv, qkvTh, qkvTl);      // 1
    ln_split_kernel<<<BT, 256>>>(x, ln1g, ln1b, hh, hl);                            // 2
    tc_gemm<false,false,false,false><<<gQ, 256, GSM_SIZE>>>(                        // 3 (PROFILED)
        hh, hl, qkvTh, qkvTl, nullptr, nullptr, qkv, nullptr, nullptr,
        QKVN, Cc, 1, QKVN);
    transpose_split_g<<<dim3(Cc/32, Cc/32, Ll), tb>>>(projw, pTh, pTl, Cc, Cc,
                                                      (size_t)Cc*Cc, (size_t)Cc*Cc);
    transpose_split_g<<<dim3(DFF/32, Cc/32, Ll), tb>>>(w1, w1Th, w1Tl, Cc, DFF,
                                                       (size_t)Cc*DFF, (size_t)Cc*DFF);
    transpose_split_g<<<dim3(Cc/32, DFF/32, Ll), tb>>>(w2, w2Th, w2Tl, DFF, Cc,
                                                       (size_t)Cc*DFF, (size_t)Cc*DFF);
    transpose_split_g<<<dim3(VPAD/32, Cc/32, 1), tb>>>(lmw, lmTh, lmTl, Cc, Vv, 0, 0);

    for (int l = 0; l < Ll; l++) {
        size_t oQ = (size_t)l * QKVN * Cc;
        size_t o2 = (size_t)l * Cc * Cc;
        size_t oF = (size_t)l * Cc * DFF;

        if (l > 0) {
            ln_split_kernel<<<BT, 256>>>(x, ln1g + l*Cc, ln1b + l*Cc, hh, hl);
            tc_gemm<false,false,false,false><<<gQ, 256, GSM_SIZE>>>(
                hh, hl, qkvTh + oQ, qkvTl + oQ, nullptr, nullptr, qkv,
                nullptr, nullptr, QKVN, Cc, 1, QKVN);
        }

        attn_kernel<<<Bb * Hh, 128, ATTN_SMEM>>>(qkv, ah, al);

        tc_gemm<true,false,true,false><<<gC, 256, GSM_SIZE>>>(
            ah, al, pTh + o2, pTl + o2, projb + l*Cc, x, x, nullptr, nullptr,
            Cc, Cc, 1, Cc);

        ln_split_kernel<<<BT, 256>>>(x, ln2g + l*Cc, ln2b + l*Cc, hh, hl);

        tc_gemm<true,true,false,true><<<gF, 256, GSM_SIZE>>>(
            hh, hl, w1Th + oF, w1Tl + oF, b1 + l*DFF, nullptr, nullptr, fh, fl,
            DFF, Cc, 1, DFF);

        tc_gemm<true,false,true,false><<<gC, 256, GSM_SIZE>>>(
            fh, fl, w2Th + oF, w2Tl + oF, b2 + l*Cc, x, x, nullptr, nullptr,
            Cc, DFF, 1, Cc);
    }

    ln_split_kernel<<<BT, 256>>>(x, lnfg, lnfb, hh, hl);

    tc_gemm<true,false,false,false><<<gV, 256, GSM_SIZE>>>(
        hh, hl, lmTh, lmTl, lmb, nullptr, out, nullptr, nullptr,
        Vv, Cc, 4, VPAD);
}

// round 8
// speedup vs baseline: 2.3225x; 2.3225x over previous
#include <cuda_runtime.h>
#include <cuda_bf16.h>
#include <math.h>
#include <cstdint>

// tcgen05 is only legal on arch-specific targets (sm_103a / sm_100a).
// The harness's nvcc also runs a generic compute_103 PTX pass; guard so that
// pass compiles empty bodies (the sm_103a cubin is what actually runs).
#if !defined(__CUDA_ARCH__) || defined(__CUDA_ARCH_FEAT_SM103_ALL) || \
    defined(__CUDA_ARCH_FEAT_SM100_ALL) || defined(__CUDA_ARCH_FEAT_SM101_ALL)
#define HAS_TCGEN05 1
#else
#define HAS_TCGEN05 0
#endif

// Problem dims
#define Bb   128
#define Tt   128
#define Cc   256
#define Hh   4
#define HS   64
#define Ll   6
#define DFF  1024
#define Vv   10000
#define BT   (Bb*Tt)   // 16384
#define VPAD 10240     // 80*128 (LM head padded to 4-tile groups)
#define QKVN 768

// ================= PTX helpers (sm_103a tcgen05) ===========================
__device__ __forceinline__ uint32_t smem_to_u32(const void* p) {
    uint32_t a;
    asm("{ .reg .u64 t; cvta.to.shared.u64 t, %1; cvt.u32.u64 %0, t; }"
        : "=r"(a) : "l"(p));
    return a;
}

#if HAS_TCGEN05
__device__ __forceinline__ uint32_t elect_one_pred() {
    uint32_t pred;
    asm volatile(
        "{\n\t.reg .pred p;\n\telect.sync _|p, 0xFFFFFFFF;\n\t"
        "selp.b32 %0, 1, 0, p;\n\t}"
        : "=r"(pred));
    return pred;
}
#define TCGEN05_ALLOC(smem_addr, nCols) \
    asm volatile("tcgen05.alloc.cta_group::1.sync.aligned.shared::cta.b32 [%0], %1;" \
        :: "r"((uint32_t)(smem_addr)), "r"((uint32_t)(nCols)) : "memory")
#define TCGEN05_DEALLOC(tmem_addr, nCols) \
    asm volatile("tcgen05.dealloc.cta_group::1.sync.aligned.b32 %0, %1;" \
        :: "r"(tmem_addr), "r"((uint32_t)(nCols)))
#define TCGEN05_RELINQ() \
    asm volatile("tcgen05.relinquish_alloc_permit.cta_group::1.sync.aligned;")
#define TCGEN05_COMMIT(mbar) \
    asm volatile("tcgen05.commit.cta_group::1.mbarrier::arrive::one.shared::cluster.b64 [%0];" \
        :: "r"((uint32_t)(mbar)) : "memory")
#define TCGEN05_FENCE_BEFORE() \
    asm volatile("tcgen05.fence::before_thread_sync;" ::: "memory")
#define TCGEN05_FENCE_AFTER() \
    asm volatile("tcgen05.fence::after_thread_sync;" ::: "memory")
#define TCGEN05_WAIT_LD() \
    asm volatile("tcgen05.wait::ld.sync.aligned;" ::: "memory")
#define FENCE_PROXY_ASYNC_SHARED_CTA() \
    asm volatile("fence.proxy.async.shared::cta;" ::: "memory")
#define MBARRIER_INIT(mbar, count) \
    asm volatile("mbarrier.init.shared.b64 [%0], %1;" \
        :: "r"((uint32_t)(mbar)), "r"((uint32_t)(count)) : "memory")
#define MBARRIER_INVAL(mbar) \
    asm volatile("mbarrier.inval.shared.b64 [%0];" :: "r"((uint32_t)(mbar)) : "memory")
// Non-blocking poll: mbarrier.test_wait in a spin loop, no sleep.
#define MBARRIER_POLL(mbar, parity) do { \
    uint32_t _mbar = (uint32_t)(mbar); \
    uint32_t _par  = (uint32_t)(parity); \
    uint32_t _done = 0; \
    while (!_done) { \
        asm volatile( \
            "{\n\t.reg .pred p;\n\t" \
            "mbarrier.test_wait.parity.acquire.cta.shared::cta.b64 p, [%1], %2;\n\t" \
            "selp.b32 %0, 1, 0, p;\n\t}" \
            : "=r"(_done) : "r"(_mbar), "r"(_par) : "memory"); \
    } \
} while (0)
// Async 16B copy global->shared (LDGSTS). Register-free, deep MLP.
__device__ __forceinline__ void cp_async16(uint32_t dst, const void* src) {
    asm volatile("cp.async.cg.shared.global [%0], [%1], 16;"
        :: "r"(dst), "l"(src) : "memory");
}
#define CP_ASYNC_COMMIT() asm volatile("cp.async.commit_group;" ::: "memory")
#define CP_ASYNC_WAIT0()  asm volatile("cp.async.wait_group 0;" ::: "memory")
#define TCGEN05_LD_32X32B_X32(r, tmem_addr) \
    asm volatile( \
        "tcgen05.ld.sync.aligned.32x32b.x32.b32 " \
        "{%0, %1, %2, %3, %4, %5, %6, %7, " \
        " %8, %9, %10, %11, %12, %13, %14, %15, " \
        " %16, %17, %18, %19, %20, %21, %22, %23, " \
        " %24, %25, %26, %27, %28, %29, %30, %31}, [%32];" \
        : "=r"((r)[0]),  "=r"((r)[1]),  "=r"((r)[2]),  "=r"((r)[3]), \
          "=r"((r)[4]),  "=r"((r)[5]),  "=r"((r)[6]),  "=r"((r)[7]), \
          "=r"((r)[8]),  "=r"((r)[9]),  "=r"((r)[10]), "=r"((r)[11]), \
          "=r"((r)[12]), "=r"((r)[13]), "=r"((r)[14]), "=r"((r)[15]), \
          "=r"((r)[16]), "=r"((r)[17]), "=r"((r)[18]), "=r"((r)[19]), \
          "=r"((r)[20]), "=r"((r)[21]), "=r"((r)[22]), "=r"((r)[23]), \
          "=r"((r)[24]), "=r"((r)[25]), "=r"((r)[26]), "=r"((r)[27]), \
          "=r"((r)[28]), "=r"((r)[29]), "=r"((r)[30]), "=r"((r)[31]) \
        : "r"(tmem_addr))

// cg1 bf16 SS MMA (A in SMEM, B in SMEM), fp32 accumulate
__device__ __forceinline__ void mma_bf16_ss(uint32_t d, uint64_t a, uint64_t b,
                                            uint32_t idesc, bool en) {
    uint32_t e = en ? 1u : 0u;
    asm volatile(
        "{\n\t.reg .pred p;\n\t"
        "setp.ne.u32 p, %5, 0;\n\t"
        "tcgen05.mma.cta_group::1.kind::f16 [%0], %1, %2, %3, {%4, %4, %4, %4}, p;\n\t}"
        :: "r"(d), "l"(a), "l"(b), "r"(idesc), "r"(0u), "r"(e)
        : "memory");
}
#endif  // HAS_TCGEN05

// 64-bit SMEM descriptor: SW128, Blackwell v1, LBO=1, SBO=64 (K-major 128B rows)
static __device__ __forceinline__ uint64_t make_desc_sw128(uint32_t addr) {
    const uint64_t base =
        (uint64_t(2)  << 61) | (uint64_t(1) << 46) |
        (uint64_t(64) << 32) | (uint64_t(1) << 16);
    return base | ((uint64_t)(addr >> 4) & 0x3FFF);
}
#define SW128(bo) ((bo) ^ (((bo) >> 3) & 0x70))

// ================= scratch (device globals) ================================
__device__ __align__(16) float g_x  [BT*Cc];
__device__ __align__(16) float g_qkv[BT*QKVN];
// bf16 hi/lo activations
__device__ __align__(16) __nv_bfloat16 g_hh[BT*Cc],  g_hl[BT*Cc];
__device__ __align__(16) __nv_bfloat16 g_ah[BT*Cc],  g_al[BT*Cc];
__device__ __align__(16) __nv_bfloat16 g_fh[BT*DFF], g_fl[BT*DFF];
// transposed+split weights: [N(pad), K] K-major
__device__ __align__(16) __nv_bfloat16 g_qkvT_h[Ll*QKVN*Cc], g_qkvT_l[Ll*QKVN*Cc];
__device__ __align__(16) __nv_bfloat16 g_pT_h [Ll*Cc*Cc],    g_pT_l [Ll*Cc*Cc];
__device__ __align__(16) __nv_bfloat16 g_w1T_h[Ll*DFF*Cc],   g_w1T_l[Ll*DFF*Cc];
__device__ __align__(16) __nv_bfloat16 g_w2T_h[Ll*Cc*DFF],   g_w2T_l[Ll*Cc*DFF];
__device__ __align__(16) __nv_bfloat16 g_lmT_h[VPAD*Cc],     g_lmT_l[VPAD*Cc];

// ================= small kernels ===========================================
__global__ void embed_kernel(const int* __restrict__ idx,
                             const float* __restrict__ tok,
                             const float* __restrict__ pos,
                             float* __restrict__ x) {
    int i = blockIdx.x * blockDim.x + threadIdx.x;
    const int total = BT * Cc;
    for (; i < total; i += gridDim.x * blockDim.x) {
        int row = i >> 8;
        int c   = i & 255;
        int t   = row & (Tt - 1);
        x[i] = tok[idx[row] * Cc + c] + pos[t * Cc + c];
    }
}

// generic: W [K,N] fp32 (layer-strided) -> out [Npad,K] bf16 hi/lo
__global__ void transpose_split_g(const float* __restrict__ W,
                                  __nv_bfloat16* __restrict__ oh,
                                  __nv_bfloat16* __restrict__ ol,
                                  int K, int N,
                                  size_t wstride, size_t ostride) {
    __shared__ float t[32][33];
    int l  = blockIdx.z;
    W  += (size_t)l * wstride;
    oh += (size_t)l * ostride;
    ol += (size_t)l * ostride;
    int n0 = blockIdx.x * 32, k0 = blockIdx.y * 32;
    int tx = threadIdx.x, ty = threadIdx.y;
    #pragma unroll
    for (int i = 0; i < 4; i++) {
        int k = k0 + ty + i * 8;
        int n = n0 + tx;
        t[ty + i * 8][tx] = (n < N) ? W[(size_t)k * N + n] : 0.f;
    }
    __syncthreads();
    #pragma unroll
    for (int i = 0; i < 4; i++) {
        int n = n0 + ty + i * 8;
        int k = k0 + tx;
        float v = t[tx][ty + i * 8];
        __nv_bfloat16 hi = __float2bfloat16(v);
        oh[(size_t)n * K + k] = hi;
        ol[(size_t)n * K + k] = __float2bfloat16(v - __bfloat162float(hi));
    }
}

// fused QKV transpose: wq/wk/wv [L][256][256] -> out [L][768][256]
__global__ void qkv_transpose(const float* __restrict__ wq,
                              const float* __restrict__ wk,
                              const float* __restrict__ wv,
                              __nv_bfloat16* __restrict__ oh,
                              __nv_bfloat16* __restrict__ ol) {
    __shared__ float t[32][33];
    int l  = blockIdx.z;
    int n0 = blockIdx.x * 32, k0 = blockIdx.y * 32;
    const float* W;
    int nb;
    if      (n0 < 256) { W = wq + (size_t)l * Cc * Cc; nb = n0; }
    else if (n0 < 512) { W = wk + (size_t)l * Cc * Cc; nb = n0 - 256; }
    else               { W = wv + (size_t)l * Cc * Cc; nb = n0 - 512; }
    oh += (size_t)l * QKVN * Cc;
    ol += (size_t)l * QKVN * Cc;
    int tx = threadIdx.x, ty = threadIdx.y;
    #pragma unroll
    for (int i = 0; i < 4; i++) {
        int k = k0 + ty + i * 8;
        t[ty + i * 8][tx] = W[(size_t)k * Cc + nb + tx];
    }
    __syncthreads();
    #pragma unroll
    for (int i = 0; i < 4; i++) {
        int n = n0 + ty + i * 8;
        int k = k0 + tx;
        float v = t[tx][ty + i * 8];
        __nv_bfloat16 hi = __float2bfloat16(v);
        oh[(size_t)n * Cc + k] = hi;
        ol[(size_t)n * Cc + k] = __float2bfloat16(v - __bfloat162float(hi));
    }
}

// LayerNorm, outputs bf16 hi/lo split
__global__ void ln_split_kernel(const float* __restrict__ x,
                                const float* __restrict__ g,
                                const float* __restrict__ b,
                                __nv_bfloat16* __restrict__ oh,
                                __nv_bfloat16* __restrict__ ol) {
    int row = blockIdx.x;
    int tid = threadIdx.x;
    float v = x[row * Cc + tid];
    float s = v, s2 = v * v;
    #pragma unroll
    for (int off = 16; off > 0; off >>= 1) {
        s  += __shfl_xor_sync(0xffffffffu, s,  off);
        s2 += __shfl_xor_sync(0xffffffffu, s2, off);
    }
    __shared__ float ss[8], ss2[8];
    __shared__ float mean_s, rstd_s;
    int w = tid >> 5, l = tid & 31;
    if (l == 0) { ss[w] = s; ss2[w] = s2; }
    __syncthreads();
    if (tid == 0) {
        float S = 0.f, S2 = 0.f;
        #pragma unroll
        for (int i = 0; i < 8; i++) { S += ss[i]; S2 += ss2[i]; }
        float m   = S * (1.0f / Cc);
        float var = S2 * (1.0f / Cc) - m * m;
        mean_s = m;
        rstd_s = rsqrtf(var + 1e-5f);
    }
    __syncthreads();
    float y = (v - mean_s) * rstd_s * g[tid] + b[tid];
    __nv_bfloat16 hi = __float2bfloat16(y);
    oh[row * Cc + tid] = hi;
    ol[row * Cc + tid] = __float2bfloat16(y - __bfloat162float(hi));
}

// ================= tcgen05 GEMM (cp.async loads, coalesced epilogue) ========
// C[M,N] = (Ah+Al)[M,K] @ (Bh+Bl)^T  with B stored [Npad,K] K-major.
// tile 128x128, K-chunk 64 (one SW128 atom row of 128B).
// Epilogue transposes D through smem so global stores are fully coalesced —
// the direct LDTM->STG path had lane=row => 32 sectors per STG (8-16x write
// amplification; the R5-R7 phantom L2 traffic).
#define GSM_TPTR 0
#define GSM_MBAR 8
#define GSM_AH   1024
#define GSM_AL   (1024 + 16384)
#define GSM_BH   (1024 + 32768)
#define GSM_BL   (1024 + 49152)
#define EPI_PAD  132                       // fp32 row pitch (16B-aligned rows)
#define GSM_SIZE (1024 + 128*EPI_PAD*4)    // 68608 >= 1024+65536 operand area
#define GEMM_IDESC 0x8200490u   // f32 acc, bf16 a/b, N=128, M=128

template<bool BIAS, bool RELU, bool RESID, bool SPLIT>
__global__ __launch_bounds__(256)
void tc_gemm(const __nv_bfloat16* __restrict__ Ah, const __nv_bfloat16* __restrict__ Al,
             const __nv_bfloat16* __restrict__ Bh, const __nv_bfloat16* __restrict__ Bl,
             const float* __restrict__ bias, const float* __restrict__ res,
             float* __restrict__ outf,
             __nv_bfloat16* __restrict__ oh, __nv_bfloat16* __restrict__ ol,
             int Nstore, int K, int ntiles, int Npad) {
#if HAS_TCGEN05
    extern __shared__ char smem[];
    const uint32_t smem_base = smem_to_u32(smem);
    const int tid  = threadIdx.x;
    const int wid  = tid >> 5;
    const int lane = tid & 31;
    const int bm   = blockIdx.y * 128;
    const int bn0  = blockIdx.x * 128 * ntiles;

    if (wid == 0) {
        TCGEN05_ALLOC(smem_base + GSM_TPTR, 128);
        TCGEN05_RELINQ();
    }
    if (tid == 0) MBARRIER_INIT(smem_base + GSM_MBAR, 1);
    __syncthreads();
    uint32_t tmem;
    asm volatile("ld.shared.b32 %0, [%1];" : "=r"(tmem) : "r"(smem_base + GSM_TPTR));

    const uint64_t dAh = make_desc_sw128(smem_base + GSM_AH);
    const uint64_t dAl = make_desc_sw128(smem_base + GSM_AL);
    const uint64_t dBh = make_desc_sw128(smem_base + GSM_BH);
    const uint64_t dBl = make_desc_sw128(smem_base + GSM_BL);

    // per-thread load mapping: 4 iters x one 16B vector per tile buffer
    const int lr = tid >> 3;            // row base 0..31 (+32*i)
    const int lb = (tid & 7) * 16;      // byte offset in 128B row

    const int nchunks = K >> 6;   // K/64
    int cc = 0;                   // global chunk counter (mbarrier parity)

    for (int t = 0; t < ntiles; t++) {
        const int bn = bn0 + t * 128;
        if (bn >= Npad) break;

        for (int c = 0; c < nchunks; c++) {
            const int k0 = c << 6;
            #pragma unroll
            for (int i = 0; i < 4; i++) {
                int r = lr + i * 32;
                uint32_t so = SW128(r * 128 + lb);
                const char* sa = (const char*)(Ah + (size_t)(bm + r) * K + k0) + lb;
                const char* sb = (const char*)(Al + (size_t)(bm + r) * K + k0) + lb;
                const char* sc = (const char*)(Bh + (size_t)(bn + r) * K + k0) + lb;
                const char* sd = (const char*)(Bl + (size_t)(bn + r) * K + k0) + lb;
                cp_async16(smem_base + GSM_AH + so, sa);
                cp_async16(smem_base + GSM_AL + so, sb);
                cp_async16(smem_base + GSM_BH + so, sc);
                cp_async16(smem_base + GSM_BL + so, sd);
            }
            CP_ASYNC_COMMIT();
            CP_ASYNC_WAIT0();
            FENCE_PROXY_ASYNC_SHARED_CTA();
            __syncthreads();

            if (wid == 0 && elect_one_pred()) {
                #pragma unroll
                for (int ks = 0; ks < 4; ks++) {
                    uint64_t oa = (uint64_t)(ks * 2);
                    mma_bf16_ss(tmem, dAh + oa, dBh + oa, GEMM_IDESC, !(c == 0 && ks == 0));
                    mma_bf16_ss(tmem, dAh + oa, dBl + oa, GEMM_IDESC, true);
                    mma_bf16_ss(tmem, dAl + oa, dBh + oa, GEMM_IDESC, true);
                }
                TCGEN05_COMMIT(smem_base + GSM_MBAR);
            }
            // warp 0 polls (no sleep), everyone else joins at the barrier
            if (wid == 0) MBARRIER_POLL(smem_base + GSM_MBAR, cc & 1);
            __syncthreads();
            cc++;
        }
        TCGEN05_FENCE_AFTER();

        // ---- epilogue: transpose through smem, fully coalesced stores ----
        {
            float* eps = (float*)(smem + GSM_AH);   // reuse operand smem
            const int wp   = wid & 3;
            const int colg = (wid >> 2) * 64;
            const int ml   = wp * 32 + lane;        // local row (m)
            #pragma unroll
            for (int half = 0; half < 2; half++) {
                int cb = colg + half * 32;
                uint32_t r[32];
                TCGEN05_LD_32X32B_X32(r, tmem + cb);
                TCGEN05_WAIT_LD();
                #pragma unroll
                for (int j = 0; j < 32; j++)
                    eps[ml * EPI_PAD + cb + j] = __uint_as_float(r[j]);
            }
            TCGEN05_FENCE_BEFORE();
            __syncthreads();

            // 128 rows x 32 float4-cols = 4096 quads; 256 threads x 16 iters.
            // Within a warp all lanes share one row; lanes cover the full
            // 128 columns -> 512B contiguous global accesses.
            #pragma unroll 4
            for (int it = 0; it < 16; it++) {
                int q   = it * 256 + tid;
                int row = q >> 5;
                int c4  = (q & 31) << 2;
                int n   = bn + c4;
                if (n < Nstore) {
                    float4 v = *(const float4*)&eps[row * EPI_PAD + c4];
                    float vals[4] = {v.x, v.y, v.z, v.w};
                    size_t base = (size_t)(bm + row) * Nstore + n;
                    #pragma unroll
                    for (int e = 0; e < 4; e++) {
                        if (BIAS) vals[e] += bias[n + e];
                        if (RELU) vals[e] = fmaxf(vals[e], 0.f);
                    }
                    if (SPLIT) {
                        #pragma unroll
                        for (int e = 0; e < 4; e++) {
                            __nv_bfloat16 hi = __float2bfloat16(vals[e]);
                            oh[base + e] = hi;
                            ol[base + e] = __float2bfloat16(vals[e] - __bfloat162float(hi));
                        }
                    } else {
                        if (RESID) {
                            float4 rv = *(const float4*)&res[base];
                            vals[0] += rv.x; vals[1] += rv.y;
                            vals[2] += rv.z; vals[3] += rv.w;
                        }
                        float4 o;
                        o.x = vals[0]; o.y = vals[1]; o.z = vals[2]; o.w = vals[3];
                        *(float4*)&outf[base] = o;
                    }
                }
            }
            __syncthreads();   // eps dead before next tile's operand loads
        }
    }

    if (tid == 0) MBARRIER_INVAL(smem_base + GSM_MBAR);
    __syncthreads();
    if (wid == 0) TCGEN05_DEALLOC(tmem, 128);
#endif  // HAS_TCGEN05
}

// ================= fused causal attention (fused qkv in, bf16 hi/lo out) ----
#define ATTN_SMEM ((64*128 + 128*68 + 4*64) * 4)

__global__ __launch_bounds__(128)
void attn_kernel(const float* __restrict__ qkv,
                 __nv_bfloat16* __restrict__ oh, __nv_bfloat16* __restrict__ ol) {
    extern __shared__ float sm[];
    float* Kst = sm;                       // [64][128]
    float* Vs  = sm + 64 * 128;            // [128][68]
    float* qs  = sm + 64 * 128 + 128 * 68; // [4][64]

    const int b    = blockIdx.x >> 2;
    const int h    = blockIdx.x & 3;
    const int tid  = threadIdx.x;
    const int lane = tid & 31;
    const int w    = tid >> 5;

    const float* base_bt = qkv + (size_t)(b * Tt) * QKVN + h * HS;
    {
        const float* krow = base_bt + 256 + (size_t)tid * QKVN;
        const float* vrow = base_bt + 512 + (size_t)tid * QKVN;
        #pragma unroll
        for (int d4 = 0; d4 < 16; d4++) {
            float4 kv = *(const float4*)(krow + d4 * 4);
            Kst[(d4 * 4 + 0) * 128 + tid] = kv.x;
            Kst[(d4 * 4 + 1) * 128 + tid] = kv.y;
            Kst[(d4 * 4 + 2) * 128 + tid] = kv.z;
            Kst[(d4 * 4 + 3) * 128 + tid] = kv.w;
            *(float4*)&Vs[tid * 68 + d4 * 4] = *(const float4*)(vrow + d4 * 4);
        }
    }
    __syncthreads();

    const float scale = 0.0625f;  // 256^-0.5

    for (int r = 0; r < 32; r++) {
        const int qr = r * 4 + w;
        const float* qrow = base_bt + (size_t)qr * QKVN;
        qs[w * 64 + lane]      = qrow[lane];
        qs[w * 64 + lane + 32] = qrow[lane + 32];
        __syncwarp();

        float s0 = 0.f, s1 = 0.f, s2 = 0.f, s3 = 0.f;
        #pragma unroll 8
        for (int d = 0; d < 64; d++) {
            float qd = qs[w * 64 + d];
            const float* kd = &Kst[d * 128];
            s0 = fmaf(qd, kd[lane],      s0);
            s1 = fmaf(qd, kd[lane + 32], s1);
            s2 = fmaf(qd, kd[lane + 64], s2);
            s3 = fmaf(qd, kd[lane + 96], s3);
        }
        s0 *= scale; s1 *= scale; s2 *= scale; s3 *= scale;

        const int k0 = lane, k1 = lane + 32, k2 = lane + 64, k3 = lane + 96;
        float mx = -1e30f;
        if (k0 <= qr) mx = fmaxf(mx, s0);
        if (k1 <= qr) mx = fmaxf(mx, s1);
        if (k2 <= qr) mx = fmaxf(mx, s2);
        if (k3 <= qr) mx = fmaxf(mx, s3);
        #pragma unroll
        for (int off = 16; off > 0; off >>= 1)
            mx = fmaxf(mx, __shfl_xor_sync(0xffffffffu, mx, off));

        float e0 = (k0 <= qr) ? __expf(s0 - mx) : 0.f;
        float e1 = (k1 <= qr) ? __expf(s1 - mx) : 0.f;
        float e2 = (k2 <= qr) ? __expf(s2 - mx) : 0.f;
        float e3 = (k3 <= qr) ? __expf(s3 - mx) : 0.f;

        float sum = e0 + e1 + e2 + e3;
        #pragma unroll
        for (int off = 16; off > 0; off >>= 1)
            sum += __shfl_xor_sync(0xffffffffu, sum, off);
        float rs = 1.0f / sum;
        float p0 = e0 * rs, p1 = e1 * rs, p2 = e2 * rs, p3 = e3 * rs;

        float o0 = 0.f, o1 = 0.f;
        for (int kk = 0; kk <= qr; kk++) {
            float psel = (kk < 32) ? p0 : (kk < 64) ? p1 : (kk < 96) ? p2 : p3;
            float pk = __shfl_sync(0xffffffffu, psel, kk & 31);
            const float* vrow = &Vs[kk * 68];
            o0 = fmaf(pk, vrow[lane],      o0);
            o1 = fmaf(pk, vrow[lane + 32], o1);
        }

        size_t obase = (size_t)(b * Tt + qr) * Cc + h * HS;
        __nv_bfloat16 h0 = __float2bfloat16(o0);
        __nv_bfloat16 h1 = __float2bfloat16(o1);
        oh[obase + lane]      = h0;
        oh[obase + lane + 32] = h1;
        ol[obase + lane]      = __float2bfloat16(o0 - __bfloat162float(h0));
        ol[obase + lane + 32] = __float2bfloat16(o1 - __bfloat162float(h1));
        __syncwarp();
    }
}

// ================= launch ===================================================
extern "C" void kernel_launch(void* const* d_in, const int* in_sizes, int n_in,
                              void* d_out, int out_size) {
    const int*   idx   = (const int*)  d_in[0];
    const float* tok   = (const float*)d_in[1];
    const float* pos   = (const float*)d_in[2];
    const float* ln1g  = (const float*)d_in[3];
    const float* ln1b  = (const float*)d_in[4];
    const float* wq    = (const float*)d_in[5];
    const float* wk    = (const float*)d_in[6];
    const float* wv    = (const float*)d_in[7];
    const float* projw = (const float*)d_in[8];
    const float* projb = (const float*)d_in[9];
    const float* ln2g  = (const float*)d_in[10];
    const float* ln2b  = (const float*)d_in[11];
    const float* w1    = (const float*)d_in[12];
    const float* b1    = (const float*)d_in[13];
    const float* w2    = (const float*)d_in[14];
    const float* b2    = (const float*)d_in[15];
    const float* lnfg  = (const float*)d_in[16];
    const float* lnfb  = (const float*)d_in[17];
    const float* lmw   = (const float*)d_in[18];
    const float* lmb   = (const float*)d_in[19];
    float* out = (float*)d_out;

    float *x, *qkv;
    __nv_bfloat16 *hh, *hl, *ah, *al, *fh, *fl;
    __nv_bfloat16 *qkvTh, *qkvTl, *pTh, *pTl;
    __nv_bfloat16 *w1Th, *w1Tl, *w2Th, *w2Tl, *lmTh, *lmTl;
    cudaGetSymbolAddress((void**)&x,   g_x);
    cudaGetSymbolAddress((void**)&qkv, g_qkv);
    cudaGetSymbolAddress((void**)&hh, g_hh);  cudaGetSymbolAddress((void**)&hl, g_hl);
    cudaGetSymbolAddress((void**)&ah, g_ah);  cudaGetSymbolAddress((void**)&al, g_al);
    cudaGetSymbolAddress((void**)&fh, g_fh);  cudaGetSymbolAddress((void**)&fl, g_fl);
    cudaGetSymbolAddress((void**)&qkvTh, g_qkvT_h); cudaGetSymbolAddress((void**)&qkvTl, g_qkvT_l);
    cudaGetSymbolAddress((void**)&pTh,  g_pT_h);    cudaGetSymbolAddress((void**)&pTl,  g_pT_l);
    cudaGetSymbolAddress((void**)&w1Th, g_w1T_h);   cudaGetSymbolAddress((void**)&w1Tl, g_w1T_l);
    cudaGetSymbolAddress((void**)&w2Th, g_w2T_h);   cudaGetSymbolAddress((void**)&w2Tl, g_w2T_l);
    cudaGetSymbolAddress((void**)&lmTh, g_lmT_h);   cudaGetSymbolAddress((void**)&lmTl, g_lmT_l);

    cudaFuncSetAttribute(attn_kernel,
                         cudaFuncAttributeMaxDynamicSharedMemorySize, ATTN_SMEM);
    cudaFuncSetAttribute(tc_gemm<false,false,false,false>,
                         cudaFuncAttributeMaxDynamicSharedMemorySize, GSM_SIZE);
    cudaFuncSetAttribute(tc_gemm<true,false,true,false>,
                         cudaFuncAttributeMaxDynamicSharedMemorySize, GSM_SIZE);
    cudaFuncSetAttribute(tc_gemm<true,true,false,true>,
                         cudaFuncAttributeMaxDynamicSharedMemorySize, GSM_SIZE);
    cudaFuncSetAttribute(tc_gemm<true,false,false,false>,
                         cudaFuncAttributeMaxDynamicSharedMemorySize, GSM_SIZE);

    dim3 tb(32, 8);
    const dim3 gC(Cc / 128,   BT / 128);   // N=256
    const dim3 gQ(QKVN / 128, BT / 128);   // N=768
    const dim3 gF(DFF / 128,  BT / 128);   // N=1024
    const dim3 gV(VPAD / 512, BT / 128);   // LM head: 20 x 128, 4 N-tiles/CTA

    // Launch order: index 3 is the profiled launch (ncu lands on our #3).
    embed_kernel<<<2048, 256>>>(idx, tok, pos, x);                                  // 0
    qkv_transpose<<<dim3(QKVN/32, Cc/32, Ll), tb>>>(wq, wk, wv, qkvTh, qkvTl);      // 1
    ln_split_kernel<<<BT, 256>>>(x, ln1g, ln1b, hh, hl);                            // 2
    tc_gemm<false,false,false,false><<<gQ, 256, GSM_SIZE>>>(                        // 3 (PROFILED)
        hh, hl, qkvTh, qkvTl, nullptr, nullptr, qkv, nullptr, nullptr,
        QKVN, Cc, 1, QKVN);
    transpose_split_g<<<dim3(Cc/32, Cc/32, Ll), tb>>>(projw, pTh, pTl, Cc, Cc,
                                                      (size_t)Cc*Cc, (size_t)Cc*Cc);
    transpose_split_g<<<dim3(DFF/32, Cc/32, Ll), tb>>>(w1, w1Th, w1Tl, Cc, DFF,
                                                       (size_t)Cc*DFF, (size_t)Cc*DFF);
    transpose_split_g<<<dim3(Cc/32, DFF/32, Ll), tb>>>(w2, w2Th, w2Tl, DFF, Cc,
                                                       (size_t)Cc*DFF, (size_t)Cc*DFF);
    transpose_split_g<<<dim3(VPAD/32, Cc/32, 1), tb>>>(lmw, lmTh, lmTl, Cc, Vv, 0, 0);

    for (int l = 0; l < Ll; l++) {
        size_t oQ = (size_t)l * QKVN * Cc;
        size_t o2 = (size_t)l * Cc * Cc;
        size_t oF = (size_t)l * Cc * DFF;

        if (l > 0) {
            ln_split_kernel<<<BT, 256>>>(x, ln1g + l*Cc, ln1b + l*Cc, hh, hl);
            tc_gemm<false,false,false,false><<<gQ, 256, GSM_SIZE>>>(
                hh, hl, qkvTh + oQ, qkvTl + oQ, nullptr, nullptr, qkv,
                nullptr, nullptr, QKVN, Cc, 1, QKVN);
        }

        attn_kernel<<<Bb * Hh, 128, ATTN_SMEM>>>(qkv, ah, al);

        tc_gemm<true,false,true,false><<<gC, 256, GSM_SIZE>>>(
            ah, al, pTh + o2, pTl + o2, projb + l*Cc, x, x, nullptr, nullptr,
            Cc, Cc, 1, Cc);

        ln_split_kernel<<<BT, 256>>>(x, ln2g + l*Cc, ln2b + l*Cc, hh, hl);

        tc_gemm<true,true,false,true><<<gF, 256, GSM_SIZE>>>(
            hh, hl, w1Th + oF, w1Tl + oF, b1 + l*DFF, nullptr, nullptr, fh, fl,
            DFF, Cc, 1, DFF);

        tc_gemm<true,false,true,false><<<gC, 256, GSM_SIZE>>>(
            fh, fl, w2Th + oF, w2Tl + oF, b2 + l*Cc, x, x, nullptr, nullptr,
            Cc, DFF, 1, Cc);
    }

    ln_split_kernel<<<BT, 256>>>(x, lnfg, lnfb, hh, hl);

    tc_gemm<true,false,false,false><<<gV, 256, GSM_SIZE>>>(
        hh, hl, lmTh, lmTl, lmb, nullptr, out, nullptr, nullptr,
        Vv, Cc, 4, VPAD);
}

// round 9
// speedup vs baseline: 3.0567x; 1.3161x over previous
#include <cuda_runtime.h>
#include <cuda_bf16.h>
#include <math.h>
#include <cstdint>

// tcgen05 is only legal on arch-specific targets (sm_103a / sm_100a).
// The harness's nvcc also runs a generic compute_103 PTX pass; guard so that
// pass compiles empty bodies (the sm_103a cubin is what actually runs).
#if !defined(__CUDA_ARCH__) || defined(__CUDA_ARCH_FEAT_SM103_ALL) || \
    defined(__CUDA_ARCH_FEAT_SM100_ALL) || defined(__CUDA_ARCH_FEAT_SM101_ALL)
#define HAS_TCGEN05 1
#else
#define HAS_TCGEN05 0
#endif

// Problem dims
#define Bb   128
#define Tt   128
#define Cc   256
#define Hh   4
#define HS   64
#define Ll   6
#define DFF  1024
#define Vv   10000
#define BT   (Bb*Tt)   // 16384
#define VPAD 10240     // 80*128 (LM head padded to 4-tile groups)
#define QKVN 768

// ================= PTX helpers (sm_103a tcgen05) ===========================
__device__ __forceinline__ uint32_t smem_to_u32(const void* p) {
    uint32_t a;
    asm("{ .reg .u64 t; cvta.to.shared.u64 t, %1; cvt.u32.u64 %0, t; }"
        : "=r"(a) : "l"(p));
    return a;
}

#if HAS_TCGEN05
__device__ __forceinline__ uint32_t elect_one_pred() {
    uint32_t pred;
    asm volatile(
        "{\n\t.reg .pred p;\n\telect.sync _|p, 0xFFFFFFFF;\n\t"
        "selp.b32 %0, 1, 0, p;\n\t}"
        : "=r"(pred));
    return pred;
}
#define TCGEN05_ALLOC(smem_addr, nCols) \
    asm volatile("tcgen05.alloc.cta_group::1.sync.aligned.shared::cta.b32 [%0], %1;" \
        :: "r"((uint32_t)(smem_addr)), "r"((uint32_t)(nCols)) : "memory")
#define TCGEN05_DEALLOC(tmem_addr, nCols) \
    asm volatile("tcgen05.dealloc.cta_group::1.sync.aligned.b32 %0, %1;" \
        :: "r"(tmem_addr), "r"((uint32_t)(nCols)))
#define TCGEN05_RELINQ() \
    asm volatile("tcgen05.relinquish_alloc_permit.cta_group::1.sync.aligned;")
#define TCGEN05_COMMIT(mbar) \
    asm volatile("tcgen05.commit.cta_group::1.mbarrier::arrive::one.shared::cluster.b64 [%0];" \
        :: "r"((uint32_t)(mbar)) : "memory")
#define TCGEN05_FENCE_BEFORE() \
    asm volatile("tcgen05.fence::before_thread_sync;" ::: "memory")
#define TCGEN05_FENCE_AFTER() \
    asm volatile("tcgen05.fence::after_thread_sync;" ::: "memory")
#define TCGEN05_WAIT_LD() \
    asm volatile("tcgen05.wait::ld.sync.aligned;" ::: "memory")
#define FENCE_PROXY_ASYNC_SHARED_CTA() \
    asm volatile("fence.proxy.async.shared::cta;" ::: "memory")
#define MBARRIER_INIT(mbar, count) \
    asm volatile("mbarrier.init.shared.b64 [%0], %1;" \
        :: "r"((uint32_t)(mbar)), "r"((uint32_t)(count)) : "memory")
#define MBARRIER_INVAL(mbar) \
    asm volatile("mbarrier.inval.shared.b64 [%0];" :: "r"((uint32_t)(mbar)) : "memory")
// Non-blocking poll: mbarrier.test_wait in a spin loop, no sleep.
#define MBARRIER_POLL(mbar, parity) do { \
    uint32_t _mbar = (uint32_t)(mbar); \
    uint32_t _par  = (uint32_t)(parity); \
    uint32_t _done = 0; \
    while (!_done) { \
        asm volatile( \
            "{\n\t.reg .pred p;\n\t" \
            "mbarrier.test_wait.parity.acquire.cta.shared::cta.b64 p, [%1], %2;\n\t" \
            "selp.b32 %0, 1, 0, p;\n\t}" \
            : "=r"(_done) : "r"(_mbar), "r"(_par) : "memory"); \
    } \
} while (0)
// Async 16B copy global->shared (LDGSTS). Register-free, deep MLP.
__device__ __forceinline__ void cp_async16(uint32_t dst, const void* src) {
    asm volatile("cp.async.cg.shared.global [%0], [%1], 16;"
        :: "r"(dst), "l"(src) : "memory");
}
#define CP_ASYNC_COMMIT() asm volatile("cp.async.commit_group;" ::: "memory")
#define CP_ASYNC_WAIT0()  asm volatile("cp.async.wait_group 0;" ::: "memory")
#define TCGEN05_LD_32X32B_X32(r, tmem_addr) \
    asm volatile( \
        "tcgen05.ld.sync.aligned.32x32b.x32.b32 " \
        "{%0, %1, %2, %3, %4, %5, %6, %7, " \
        " %8, %9, %10, %11, %12, %13, %14, %15, " \
        " %16, %17, %18, %19, %20, %21, %22, %23, " \
        " %24, %25, %26, %27, %28, %29, %30, %31}, [%32];" \
        : "=r"((r)[0]),  "=r"((r)[1]),  "=r"((r)[2]),  "=r"((r)[3]), \
          "=r"((r)[4]),  "=r"((r)[5]),  "=r"((r)[6]),  "=r"((r)[7]), \
          "=r"((r)[8]),  "=r"((r)[9]),  "=r"((r)[10]), "=r"((r)[11]), \
          "=r"((r)[12]), "=r"((r)[13]), "=r"((r)[14]), "=r"((r)[15]), \
          "=r"((r)[16]), "=r"((r)[17]), "=r"((r)[18]), "=r"((r)[19]), \
          "=r"((r)[20]), "=r"((r)[21]), "=r"((r)[22]), "=r"((r)[23]), \
          "=r"((r)[24]), "=r"((r)[25]), "=r"((r)[26]), "=r"((r)[27]), \
          "=r"((r)[28]), "=r"((r)[29]), "=r"((r)[30]), "=r"((r)[31]) \
        : "r"(tmem_addr))

// cg1 bf16 SS MMA (A in SMEM, B in SMEM), fp32 accumulate
__device__ __forceinline__ void mma_bf16_ss(uint32_t d, uint64_t a, uint64_t b,
                                            uint32_t idesc, bool en) {
    uint32_t e = en ? 1u : 0u;
    asm volatile(
        "{\n\t.reg .pred p;\n\t"
        "setp.ne.u32 p, %5, 0;\n\t"
        "tcgen05.mma.cta_group::1.kind::f16 [%0], %1, %2, %3, {%4, %4, %4, %4}, p;\n\t}"
        :: "r"(d), "l"(a), "l"(b), "r"(idesc), "r"(0u), "r"(e)
        : "memory");
}
#endif  // HAS_TCGEN05

// 64-bit SMEM descriptor: SW128, Blackwell v1, LBO=1, SBO=64 (K-major 128B rows)
static __device__ __forceinline__ uint64_t make_desc_sw128(uint32_t addr) {
    const uint64_t base =
        (uint64_t(2)  << 61) | (uint64_t(1) << 46) |
        (uint64_t(64) << 32) | (uint64_t(1) << 16);
    return base | ((uint64_t)(addr >> 4) & 0x3FFF);
}
#define SW128(bo) ((bo) ^ (((bo) >> 3) & 0x70))

// ================= scratch (device globals) ================================
__device__ __align__(16) float g_x  [BT*Cc];
__device__ __align__(16) float g_qkv[BT*QKVN];
// bf16 hi/lo activations
__device__ __align__(16) __nv_bfloat16 g_hh[BT*Cc],  g_hl[BT*Cc];
__device__ __align__(16) __nv_bfloat16 g_ah[BT*Cc],  g_al[BT*Cc];
__device__ __align__(16) __nv_bfloat16 g_fh[BT*DFF], g_fl[BT*DFF];
// transposed+split weights: [N(pad), K] K-major
__device__ __align__(16) __nv_bfloat16 g_qkvT_h[Ll*QKVN*Cc], g_qkvT_l[Ll*QKVN*Cc];
__device__ __align__(16) __nv_bfloat16 g_pT_h [Ll*Cc*Cc],    g_pT_l [Ll*Cc*Cc];
__device__ __align__(16) __nv_bfloat16 g_w1T_h[Ll*DFF*Cc],   g_w1T_l[Ll*DFF*Cc];
__device__ __align__(16) __nv_bfloat16 g_w2T_h[Ll*Cc*DFF],   g_w2T_l[Ll*Cc*DFF];
__device__ __align__(16) __nv_bfloat16 g_lmT_h[VPAD*Cc],     g_lmT_l[VPAD*Cc];

// ================= small kernels ===========================================
// Fused embedding + LN1(layer 0): one block per row. Writes x AND hh/hl.
__global__ void embed_ln_kernel(const int* __restrict__ idx,
                                const float* __restrict__ tok,
                                const float* __restrict__ pos,
                                const float* __restrict__ g,
                                const float* __restrict__ b,
                                float* __restrict__ x,
                                __nv_bfloat16* __restrict__ oh,
                                __nv_bfloat16* __restrict__ ol) {
    int row = blockIdx.x;
    int tid = threadIdx.x;
    int t   = row & (Tt - 1);
    float v = tok[idx[row] * Cc + tid] + pos[t * Cc + tid];
    x[row * Cc + tid] = v;
    float s = v, s2 = v * v;
    #pragma unroll
    for (int off = 16; off > 0; off >>= 1) {
        s  += __shfl_xor_sync(0xffffffffu, s,  off);
        s2 += __shfl_xor_sync(0xffffffffu, s2, off);
    }
    __shared__ float ss[8], ss2[8];
    __shared__ float mean_s, rstd_s;
    int w = tid >> 5, l = tid & 31;
    if (l == 0) { ss[w] = s; ss2[w] = s2; }
    __syncthreads();
    if (tid == 0) {
        float S = 0.f, S2 = 0.f;
        #pragma unroll
        for (int i = 0; i < 8; i++) { S += ss[i]; S2 += ss2[i]; }
        float m   = S * (1.0f / Cc);
        float var = S2 * (1.0f / Cc) - m * m;
        mean_s = m;
        rstd_s = rsqrtf(var + 1e-5f);
    }
    __syncthreads();
    float y = (v - mean_s) * rstd_s * g[tid] + b[tid];
    __nv_bfloat16 hi = __float2bfloat16(y);
    oh[row * Cc + tid] = hi;
    ol[row * Cc + tid] = __float2bfloat16(y - __bfloat162float(hi));
}

// generic: W [K,N] fp32 (layer-strided) -> out [Npad,K] bf16 hi/lo
__global__ void transpose_split_g(const float* __restrict__ W,
                                  __nv_bfloat16* __restrict__ oh,
                                  __nv_bfloat16* __restrict__ ol,
                                  int K, int N,
                                  size_t wstride, size_t ostride) {
    __shared__ float t[32][33];
    int l  = blockIdx.z;
    W  += (size_t)l * wstride;
    oh += (size_t)l * ostride;
    ol += (size_t)l * ostride;
    int n0 = blockIdx.x * 32, k0 = blockIdx.y * 32;
    int tx = threadIdx.x, ty = threadIdx.y;
    #pragma unroll
    for (int i = 0; i < 4; i++) {
        int k = k0 + ty + i * 8;
        int n = n0 + tx;
        t[ty + i * 8][tx] = (n < N) ? W[(size_t)k * N + n] : 0.f;
    }
    __syncthreads();
    #pragma unroll
    for (int i = 0; i < 4; i++) {
        int n = n0 + ty + i * 8;
        int k = k0 + tx;
        float v = t[tx][ty + i * 8];
        __nv_bfloat16 hi = __float2bfloat16(v);
        oh[(size_t)n * K + k] = hi;
        ol[(size_t)n * K + k] = __float2bfloat16(v - __bfloat162float(hi));
    }
}

// fused QKV transpose: wq/wk/wv [L][256][256] -> out [L][768][256]
__global__ void qkv_transpose(const float* __restrict__ wq,
                              const float* __restrict__ wk,
                              const float* __restrict__ wv,
                              __nv_bfloat16* __restrict__ oh,
                              __nv_bfloat16* __restrict__ ol) {
    __shared__ float t[32][33];
    int l  = blockIdx.z;
    int n0 = blockIdx.x * 32, k0 = blockIdx.y * 32;
    const float* W;
    int nb;
    if      (n0 < 256) { W = wq + (size_t)l * Cc * Cc; nb = n0; }
    else if (n0 < 512) { W = wk + (size_t)l * Cc * Cc; nb = n0 - 256; }
    else               { W = wv + (size_t)l * Cc * Cc; nb = n0 - 512; }
    oh += (size_t)l * QKVN * Cc;
    ol += (size_t)l * QKVN * Cc;
    int tx = threadIdx.x, ty = threadIdx.y;
    #pragma unroll
    for (int i = 0; i < 4; i++) {
        int k = k0 + ty + i * 8;
        t[ty + i * 8][tx] = W[(size_t)k * Cc + nb + tx];
    }
    __syncthreads();
    #pragma unroll
    for (int i = 0; i < 4; i++) {
        int n = n0 + ty + i * 8;
        int k = k0 + tx;
        float v = t[tx][ty + i * 8];
        __nv_bfloat16 hi = __float2bfloat16(v);
        oh[(size_t)n * Cc + k] = hi;
        ol[(size_t)n * Cc + k] = __float2bfloat16(v - __bfloat162float(hi));
    }
}

// LayerNorm, outputs bf16 hi/lo split
__global__ void ln_split_kernel(const float* __restrict__ x,
                                const float* __restrict__ g,
                                const float* __restrict__ b,
                                __nv_bfloat16* __restrict__ oh,
                                __nv_bfloat16* __restrict__ ol) {
    int row = blockIdx.x;
    int tid = threadIdx.x;
    float v = x[row * Cc + tid];
    float s = v, s2 = v * v;
    #pragma unroll
    for (int off = 16; off > 0; off >>= 1) {
        s  += __shfl_xor_sync(0xffffffffu, s,  off);
        s2 += __shfl_xor_sync(0xffffffffu, s2, off);
    }
    __shared__ float ss[8], ss2[8];
    __shared__ float mean_s, rstd_s;
    int w = tid >> 5, l = tid & 31;
    if (l == 0) { ss[w] = s; ss2[w] = s2; }
    __syncthreads();
    if (tid == 0) {
        float S = 0.f, S2 = 0.f;
        #pragma unroll
        for (int i = 0; i < 8; i++) { S += ss[i]; S2 += ss2[i]; }
        float m   = S * (1.0f / Cc);
        float var = S2 * (1.0f / Cc) - m * m;
        mean_s = m;
        rstd_s = rsqrtf(var + 1e-5f);
    }
    __syncthreads();
    float y = (v - mean_s) * rstd_s * g[tid] + b[tid];
    __nv_bfloat16 hi = __float2bfloat16(y);
    oh[row * Cc + tid] = hi;
    ol[row * Cc + tid] = __float2bfloat16(y - __bfloat162float(hi));
}

// ================= tcgen05 GEMM (cp.async loads, coalesced epilogue) ========
// Identical to R8 (the 3041us winner) — protect the win.
#define GSM_TPTR 0
#define GSM_MBAR 8
#define GSM_AH   1024
#define GSM_AL   (1024 + 16384)
#define GSM_BH   (1024 + 32768)
#define GSM_BL   (1024 + 49152)
#define EPI_PAD  132                       // fp32 row pitch (16B-aligned rows)
#define GSM_SIZE (1024 + 128*EPI_PAD*4)    // 68608 >= 1024+65536 operand area
#define GEMM_IDESC 0x8200490u   // f32 acc, bf16 a/b, N=128, M=128

template<bool BIAS, bool RELU, bool RESID, bool SPLIT>
__global__ __launch_bounds__(256)
void tc_gemm(const __nv_bfloat16* __restrict__ Ah, const __nv_bfloat16* __restrict__ Al,
             const __nv_bfloat16* __restrict__ Bh, const __nv_bfloat16* __restrict__ Bl,
             const float* __restrict__ bias, const float* __restrict__ res,
             float* __restrict__ outf,
             __nv_bfloat16* __restrict__ oh, __nv_bfloat16* __restrict__ ol,
             int Nstore, int K, int ntiles, int Npad) {
#if HAS_TCGEN05
    extern __shared__ char smem[];
    const uint32_t smem_base = smem_to_u32(smem);
    const int tid  = threadIdx.x;
    const int wid  = tid >> 5;
    const int lane = tid & 31;
    const int bm   = blockIdx.y * 128;
    const int bn0  = blockIdx.x * 128 * ntiles;

    if (wid == 0) {
        TCGEN05_ALLOC(smem_base + GSM_TPTR, 128);
        TCGEN05_RELINQ();
    }
    if (tid == 0) MBARRIER_INIT(smem_base + GSM_MBAR, 1);
    __syncthreads();
    uint32_t tmem;
    asm volatile("ld.shared.b32 %0, [%1];" : "=r"(tmem) : "r"(smem_base + GSM_TPTR));

    const uint64_t dAh = make_desc_sw128(smem_base + GSM_AH);
    const uint64_t dAl = make_desc_sw128(smem_base + GSM_AL);
    const uint64_t dBh = make_desc_sw128(smem_base + GSM_BH);
    const uint64_t dBl = make_desc_sw128(smem_base + GSM_BL);

    // per-thread load mapping: 4 iters x one 16B vector per tile buffer
    const int lr = tid >> 3;            // row base 0..31 (+32*i)
    const int lb = (tid & 7) * 16;      // byte offset in 128B row

    const int nchunks = K >> 6;   // K/64
    int cc = 0;                   // global chunk counter (mbarrier parity)

    for (int t = 0; t < ntiles; t++) {
        const int bn = bn0 + t * 128;
        if (bn >= Npad) break;

        for (int c = 0; c < nchunks; c++) {
            const int k0 = c << 6;
            #pragma unroll
            for (int i = 0; i < 4; i++) {
                int r = lr + i * 32;
                uint32_t so = SW128(r * 128 + lb);
                const char* sa = (const char*)(Ah + (size_t)(bm + r) * K + k0) + lb;
                const char* sb = (const char*)(Al + (size_t)(bm + r) * K + k0) + lb;
                const char* sc = (const char*)(Bh + (size_t)(bn + r) * K + k0) + lb;
                const char* sd = (const char*)(Bl + (size_t)(bn + r) * K + k0) + lb;
                cp_async16(smem_base + GSM_AH + so, sa);
                cp_async16(smem_base + GSM_AL + so, sb);
                cp_async16(smem_base + GSM_BH + so, sc);
                cp_async16(smem_base + GSM_BL + so, sd);
            }
            CP_ASYNC_COMMIT();
            CP_ASYNC_WAIT0();
            FENCE_PROXY_ASYNC_SHARED_CTA();
            __syncthreads();

            if (wid == 0 && elect_one_pred()) {
                #pragma unroll
                for (int ks = 0; ks < 4; ks++) {
                    uint64_t oa = (uint64_t)(ks * 2);
                    mma_bf16_ss(tmem, dAh + oa, dBh + oa, GEMM_IDESC, !(c == 0 && ks == 0));
                    mma_bf16_ss(tmem, dAh + oa, dBl + oa, GEMM_IDESC, true);
                    mma_bf16_ss(tmem, dAl + oa, dBh + oa, GEMM_IDESC, true);
                }
                TCGEN05_COMMIT(smem_base + GSM_MBAR);
            }
            // warp 0 polls (no sleep), everyone else joins at the barrier
            if (wid == 0) MBARRIER_POLL(smem_base + GSM_MBAR, cc & 1);
            __syncthreads();
            cc++;
        }
        TCGEN05_FENCE_AFTER();

        // ---- epilogue: transpose through smem, fully coalesced stores ----
        {
            float* eps = (float*)(smem + GSM_AH);   // reuse operand smem
            const int wp   = wid & 3;
            const int colg = (wid >> 2) * 64;
            const int ml   = wp * 32 + lane;        // local row (m)
            #pragma unroll
            for (int half = 0; half < 2; half++) {
                int cb = colg + half * 32;
                uint32_t r[32];
                TCGEN05_LD_32X32B_X32(r, tmem + cb);
                TCGEN05_WAIT_LD();
                #pragma unroll
                for (int j = 0; j < 32; j++)
                    eps[ml * EPI_PAD + cb + j] = __uint_as_float(r[j]);
            }
            TCGEN05_FENCE_BEFORE();
            __syncthreads();

            // 128 rows x 32 float4-cols = 4096 quads; 256 threads x 16 iters.
            #pragma unroll 4
            for (int it = 0; it < 16; it++) {
                int q   = it * 256 + tid;
                int row = q >> 5;
                int c4  = (q & 31) << 2;
                int n   = bn + c4;
                if (n < Nstore) {
                    float4 v = *(const float4*)&eps[row * EPI_PAD + c4];
                    float vals[4] = {v.x, v.y, v.z, v.w};
                    size_t base = (size_t)(bm + row) * Nstore + n;
                    #pragma unroll
                    for (int e = 0; e < 4; e++) {
                        if (BIAS) vals[e] += bias[n + e];
                        if (RELU) vals[e] = fmaxf(vals[e], 0.f);
                    }
                    if (SPLIT) {
                        #pragma unroll
                        for (int e = 0; e < 4; e++) {
                            __nv_bfloat16 hi = __float2bfloat16(vals[e]);
                            oh[base + e] = hi;
                            ol[base + e] = __float2bfloat16(vals[e] - __bfloat162float(hi));
                        }
                    } else {
                        if (RESID) {
                            float4 rv = *(const float4*)&res[base];
                            vals[0] += rv.x; vals[1] += rv.y;
                            vals[2] += rv.z; vals[3] += rv.w;
                        }
                        float4 o;
                        o.x = vals[0]; o.y = vals[1]; o.z = vals[2]; o.w = vals[3];
                        *(float4*)&outf[base] = o;
                    }
                }
            }
            __syncthreads();   // eps dead before next tile's operand loads
        }
    }

    if (tid == 0) MBARRIER_INVAL(smem_base + GSM_MBAR);
    __syncthreads();
    if (wid == 0) TCGEN05_DEALLOC(tmem, 128);
#endif  // HAS_TCGEN05
}

// ================= fused causal attention (256 threads, smem-p PV) ==========
// smem: Kst[64][128] + Vs[128][68] + qs[8][64] + ps[8][132]
#define ATTN_SMEM ((64*128 + 128*68 + 8*64 + 8*132) * 4)

__global__ __launch_bounds__(256)
void attn_kernel(const float* __restrict__ qkv,
                 __nv_bfloat16* __restrict__ oh, __nv_bfloat16* __restrict__ ol) {
    extern __shared__ float sm[];
    float* Kst = sm;                                 // [64][128] d-major
    float* Vs  = sm + 64 * 128;                      // [128][68]
    float* qs  = sm + 64 * 128 + 128 * 68;           // [8][64]
    float* ps  = qs + 8 * 64;                        // [8][132]

    const int b    = blockIdx.x >> 2;
    const int h    = blockIdx.x & 3;
    const int tid  = threadIdx.x;                    // 0..255
    const int lane = tid & 31;
    const int w    = tid >> 5;                       // 0..7

    const float* base_bt = qkv + (size_t)(b * Tt) * QKVN + h * HS;

    // Load K (transposed) and V: thread pair (row = tid>>1) covers one row.
    {
        const int row   = tid >> 1;
        const int dhalf = (tid & 1) * 32;
        const float* krow = base_bt + 256 + (size_t)row * QKVN + dhalf;
        const float* vrow = base_bt + 512 + (size_t)row * QKVN + dhalf;
        #pragma unroll
        for (int d4 = 0; d4 < 8; d4++) {
            int d = dhalf + d4 * 4;
            float4 kv = *(const float4*)(krow + d4 * 4);
            Kst[(d + 0) * 128 + row] = kv.x;
            Kst[(d + 1) * 128 + row] = kv.y;
            Kst[(d + 2) * 128 + row] = kv.z;
            Kst[(d + 3) * 128 + row] = kv.w;
            *(float4*)&Vs[row * 68 + d] = *(const float4*)(vrow + d4 * 4);
        }
    }
    __syncthreads();

    const float scale = 0.0625f;  // 256^-0.5

    for (int r = 0; r < 16; r++) {
        const int qr = r * 8 + w;   // interleave rows across 8 warps
        const float* qrow = base_bt + (size_t)qr * QKVN;
        qs[w * 64 + lane]      = qrow[lane];
        qs[w * 64 + lane + 32] = qrow[lane + 32];
        __syncwarp();

        float s0 = 0.f, s1 = 0.f, s2 = 0.f, s3 = 0.f;
        #pragma unroll 8
        for (int d = 0; d < 64; d++) {
            float qd = qs[w * 64 + d];
            const float* kd = &Kst[d * 128];
            s0 = fmaf(qd, kd[lane],      s0);
            s1 = fmaf(qd, kd[lane + 32], s1);
            s2 = fmaf(qd, kd[lane + 64], s2);
            s3 = fmaf(qd, kd[lane + 96], s3);
        }
        s0 *= scale; s1 *= scale; s2 *= scale; s3 *= scale;

        const int k0 = lane, k1 = lane + 32, k2 = lane + 64, k3 = lane + 96;
        float mx = -1e30f;
        if (k0 <= qr) mx = fmaxf(mx, s0);
        if (k1 <= qr) mx = fmaxf(mx, s1);
        if (k2 <= qr) mx = fmaxf(mx, s2);
        if (k3 <= qr) mx = fmaxf(mx, s3);
        #pragma unroll
        for (int off = 16; off > 0; off >>= 1)
            mx = fmaxf(mx, __shfl_xor_sync(0xffffffffu, mx, off));

        float e0 = (k0 <= qr) ? __expf(s0 - mx) : 0.f;
        float e1 = (k1 <= qr) ? __expf(s1 - mx) : 0.f;
        float e2 = (k2 <= qr) ? __expf(s2 - mx) : 0.f;
        float e3 = (k3 <= qr) ? __expf(s3 - mx) : 0.f;

        float sum = e0 + e1 + e2 + e3;
        #pragma unroll
        for (int off = 16; off > 0; off >>= 1)
            sum += __shfl_xor_sync(0xffffffffu, sum, off);
        float rs = 1.0f / sum;

        // stage probabilities in smem (replaces serial shfl broadcast)
        ps[w * 132 + k0] = e0 * rs;
        ps[w * 132 + k1] = e1 * rs;
        ps[w * 132 + k2] = e2 * rs;
        ps[w * 132 + k3] = e3 * rs;
        __syncwarp();

        float o0 = 0.f, o1 = 0.f;
        const float* pw = &ps[w * 132];
        #pragma unroll 4
        for (int kk = 0; kk <= qr; kk++) {
            float pk = pw[kk];                 // LDS broadcast
            const float* vrow = &Vs[kk * 68];
            o0 = fmaf(pk, vrow[lane],      o0);
            o1 = fmaf(pk, vrow[lane + 32], o1);
        }

        size_t obase = (size_t)(b * Tt + qr) * Cc + h * HS;
        __nv_bfloat16 h0 = __float2bfloat16(o0);
        __nv_bfloat16 h1 = __float2bfloat16(o1);
        oh[obase + lane]      = h0;
        oh[obase + lane + 32] = h1;
        ol[obase + lane]      = __float2bfloat16(o0 - __bfloat162float(h0));
        ol[obase + lane + 32] = __float2bfloat16(o1 - __bfloat162float(h1));
        __syncwarp();   // qs/ps reused next iteration
    }
}

// ================= launch ===================================================
extern "C" void kernel_launch(void* const* d_in, const int* in_sizes, int n_in,
                              void* d_out, int out_size) {
    const int*   idx   = (const int*)  d_in[0];
    const float* tok   = (const float*)d_in[1];
    const float* pos   = (const float*)d_in[2];
    const float* ln1g  = (const float*)d_in[3];
    const float* ln1b  = (const float*)d_in[4];
    const float* wq    = (const float*)d_in[5];
    const float* wk    = (const float*)d_in[6];
    const float* wv    = (const float*)d_in[7];
    const float* projw = (const float*)d_in[8];
    const float* projb = (const float*)d_in[9];
    const float* ln2g  = (const float*)d_in[10];
    const float* ln2b  = (const float*)d_in[11];
    const float* w1    = (const float*)d_in[12];
    const float* b1    = (const float*)d_in[13];
    const float* w2    = (const float*)d_in[14];
    const float* b2    = (const float*)d_in[15];
    const float* lnfg  = (const float*)d_in[16];
    const float* lnfb  = (const float*)d_in[17];
    const float* lmw   = (const float*)d_in[18];
    const float* lmb   = (const float*)d_in[19];
    float* out = (float*)d_out;

    float *x, *qkv;
    __nv_bfloat16 *hh, *hl, *ah, *al, *fh, *fl;
    __nv_bfloat16 *qkvTh, *qkvTl, *pTh, *pTl;
    __nv_bfloat16 *w1Th, *w1Tl, *w2Th, *w2Tl, *lmTh, *lmTl;
    cudaGetSymbolAddress((void**)&x,   g_x);
    cudaGetSymbolAddress((void**)&qkv, g_qkv);
    cudaGetSymbolAddress((void**)&hh, g_hh);  cudaGetSymbolAddress((void**)&hl, g_hl);
    cudaGetSymbolAddress((void**)&ah, g_ah);  cudaGetSymbolAddress((void**)&al, g_al);
    cudaGetSymbolAddress((void**)&fh, g_fh);  cudaGetSymbolAddress((void**)&fl, g_fl);
    cudaGetSymbolAddress((void**)&qkvTh, g_qkvT_h); cudaGetSymbolAddress((void**)&qkvTl, g_qkvT_l);
    cudaGetSymbolAddress((void**)&pTh,  g_pT_h);    cudaGetSymbolAddress((void**)&pTl,  g_pT_l);
    cudaGetSymbolAddress((void**)&w1Th, g_w1T_h);   cudaGetSymbolAddress((void**)&w1Tl, g_w1T_l);
    cudaGetSymbolAddress((void**)&w2Th, g_w2T_h);   cudaGetSymbolAddress((void**)&w2Tl, g_w2T_l);
    cudaGetSymbolAddress((void**)&lmTh, g_lmT_h);   cudaGetSymbolAddress((void**)&lmTl, g_lmT_l);

    cudaFuncSetAttribute(attn_kernel,
                         cudaFuncAttributeMaxDynamicSharedMemorySize, ATTN_SMEM);
    cudaFuncSetAttribute(tc_gemm<false,false,false,false>,
                         cudaFuncAttributeMaxDynamicSharedMemorySize, GSM_SIZE);
    cudaFuncSetAttribute(tc_gemm<true,false,true,false>,
                         cudaFuncAttributeMaxDynamicSharedMemorySize, GSM_SIZE);
    cudaFuncSetAttribute(tc_gemm<true,true,false,true>,
                         cudaFuncAttributeMaxDynamicSharedMemorySize, GSM_SIZE);
    cudaFuncSetAttribute(tc_gemm<true,false,false,false>,
                         cudaFuncAttributeMaxDynamicSharedMemorySize, GSM_SIZE);

    dim3 tb(32, 8);
    const dim3 gC(Cc / 128,   BT / 128);   // N=256
    const dim3 gQ(QKVN / 128, BT / 128);   // N=768
    const dim3 gF(DFF / 128,  BT / 128);   // N=1024
    const dim3 gV(VPAD / 512, BT / 128);   // LM head: 20 x 128, 4 N-tiles/CTA

    // Launch order: index 3 is the profiled launch -> attn_kernel this round.
    qkv_transpose<<<dim3(QKVN/32, Cc/32, Ll), tb>>>(wq, wk, wv, qkvTh, qkvTl);      // 0
    embed_ln_kernel<<<BT, 256>>>(idx, tok, pos, ln1g, ln1b, x, hh, hl);             // 1
    tc_gemm<false,false,false,false><<<gQ, 256, GSM_SIZE>>>(                        // 2
        hh, hl, qkvTh, qkvTl, nullptr, nullptr, qkv, nullptr, nullptr,
        QKVN, Cc, 1, QKVN);
    attn_kernel<<<Bb * Hh, 256, ATTN_SMEM>>>(qkv, ah, al);                          // 3 (PROFILED)
    transpose_split_g<<<dim3(Cc/32, Cc/32, Ll), tb>>>(projw, pTh, pTl, Cc, Cc,
                                                      (size_t)Cc*Cc, (size_t)Cc*Cc);
    transpose_split_g<<<dim3(DFF/32, Cc/32, Ll), tb>>>(w1, w1Th, w1Tl, Cc, DFF,
                                                       (size_t)Cc*DFF, (size_t)Cc*DFF);
    transpose_split_g<<<dim3(Cc/32, DFF/32, Ll), tb>>>(w2, w2Th, w2Tl, DFF, Cc,
                                                       (size_t)Cc*DFF, (size_t)Cc*DFF);
    transpose_split_g<<<dim3(VPAD/32, Cc/32, 1), tb>>>(lmw, lmTh, lmTl, Cc, Vv, 0, 0);

    for (int l = 0; l < Ll; l++) {
        size_t oQ = (size_t)l * QKVN * Cc;
        size_t o2 = (size_t)l * Cc * Cc;
        size_t oF = (size_t)l * Cc * DFF;

        if (l > 0) {
            ln_split_kernel<<<BT, 256>>>(x, ln1g + l*Cc, ln1b + l*Cc, hh, hl);
            tc_gemm<false,false,false,false><<<gQ, 256, GSM_SIZE>>>(
                hh, hl, qkvTh + oQ, qkvTl + oQ, nullptr, nullptr, qkv,
                nullptr, nullptr, QKVN, Cc, 1, QKVN);
            attn_kernel<<<Bb * Hh, 256, ATTN_SMEM>>>(qkv, ah, al);
        }

        tc_gemm<true,false,true,false><<<gC, 256, GSM_SIZE>>>(
            ah, al, pTh + o2, pTl + o2, projb + l*Cc, x, x, nullptr, nullptr,
            Cc, Cc, 1, Cc);

        ln_split_kernel<<<BT, 256>>>(x, ln2g + l*Cc, ln2b + l*Cc, hh, hl);

        tc_gemm<true,true,false,true><<<gF, 256, GSM_SIZE>>>(
            hh, hl, w1Th + oF, w1Tl + oF, b1 + l*DFF, nullptr, nullptr, fh, fl,
            DFF, Cc, 1, DFF);

        tc_gemm<true,false,true,false><<<gC, 256, GSM_SIZE>>>(
            fh, fl, w2Th + oF, w2Tl + oF, b2 + l*Cc, x, x, nullptr, nullptr,
            Cc, DFF, 1, Cc);
    }

    ln_split_kernel<<<BT, 256>>>(x, lnfg, lnfb, hh, hl);

    tc_gemm<true,false,false,false><<<gV, 256, GSM_SIZE>>>(
        hh, hl, lmTh, lmTl, lmb, nullptr, out, nullptr, nullptr,
        Vv, Cc, 4, VPAD);
}

// round 10
// speedup vs baseline: 3.7981x; 1.2425x over previous
#include <cuda_runtime.h>
#include <cuda_bf16.h>
#include <math.h>
#include <cstdint>

// tcgen05 is only legal on arch-specific targets (sm_103a / sm_100a).
// The harness's nvcc also runs a generic compute_103 PTX pass; guard so that
// pass compiles empty bodies (the sm_103a cubin is what actually runs).
#if !defined(__CUDA_ARCH__) || defined(__CUDA_ARCH_FEAT_SM103_ALL) || \
    defined(__CUDA_ARCH_FEAT_SM100_ALL) || defined(__CUDA_ARCH_FEAT_SM101_ALL)
#define HAS_TCGEN05 1
#else
#define HAS_TCGEN05 0
#endif

// Problem dims
#define Bb   128
#define Tt   128
#define Cc   256
#define Hh   4
#define HS   64
#define Ll   6
#define DFF  1024
#define Vv   10000
#define BT   (Bb*Tt)   // 16384
#define VPAD 10240     // 80*128 (LM head padded to 4-tile groups)
#define QKVN 768

// ================= PTX helpers (sm_103a tcgen05) ===========================
__device__ __forceinline__ uint32_t smem_to_u32(const void* p) {
    uint32_t a;
    asm("{ .reg .u64 t; cvta.to.shared.u64 t, %1; cvt.u32.u64 %0, t; }"
        : "=r"(a) : "l"(p));
    return a;
}

#if HAS_TCGEN05
__device__ __forceinline__ uint32_t elect_one_pred() {
    uint32_t pred;
    asm volatile(
        "{\n\t.reg .pred p;\n\telect.sync _|p, 0xFFFFFFFF;\n\t"
        "selp.b32 %0, 1, 0, p;\n\t}"
        : "=r"(pred));
    return pred;
}
#define TCGEN05_ALLOC(smem_addr, nCols) \
    asm volatile("tcgen05.alloc.cta_group::1.sync.aligned.shared::cta.b32 [%0], %1;" \
        :: "r"((uint32_t)(smem_addr)), "r"((uint32_t)(nCols)) : "memory")
#define TCGEN05_DEALLOC(tmem_addr, nCols) \
    asm volatile("tcgen05.dealloc.cta_group::1.sync.aligned.b32 %0, %1;" \
        :: "r"(tmem_addr), "r"((uint32_t)(nCols)))
#define TCGEN05_RELINQ() \
    asm volatile("tcgen05.relinquish_alloc_permit.cta_group::1.sync.aligned;")
#define TCGEN05_COMMIT(mbar) \
    asm volatile("tcgen05.commit.cta_group::1.mbarrier::arrive::one.shared::cluster.b64 [%0];" \
        :: "r"((uint32_t)(mbar)) : "memory")
#define TCGEN05_FENCE_BEFORE() \
    asm volatile("tcgen05.fence::before_thread_sync;" ::: "memory")
#define TCGEN05_FENCE_AFTER() \
    asm volatile("tcgen05.fence::after_thread_sync;" ::: "memory")
#define TCGEN05_WAIT_LD() \
    asm volatile("tcgen05.wait::ld.sync.aligned;" ::: "memory")
#define FENCE_PROXY_ASYNC_SHARED_CTA() \
    asm volatile("fence.proxy.async.shared::cta;" ::: "memory")
#define MBARRIER_INIT(mbar, count) \
    asm volatile("mbarrier.init.shared.b64 [%0], %1;" \
        :: "r"((uint32_t)(mbar)), "r"((uint32_t)(count)) : "memory")
#define MBARRIER_INVAL(mbar) \
    asm volatile("mbarrier.inval.shared.b64 [%0];" :: "r"((uint32_t)(mbar)) : "memory")
// Non-blocking poll: mbarrier.test_wait in a spin loop, no sleep.
#define MBARRIER_POLL(mbar, parity) do { \
    uint32_t _mbar = (uint32_t)(mbar); \
    uint32_t _par  = (uint32_t)(parity); \
    uint32_t _done = 0; \
    while (!_done) { \
        asm volatile( \
            "{\n\t.reg .pred p;\n\t" \
            "mbarrier.test_wait.parity.acquire.cta.shared::cta.b64 p, [%1], %2;\n\t" \
            "selp.b32 %0, 1, 0, p;\n\t}" \
            : "=r"(_done) : "r"(_mbar), "r"(_par) : "memory"); \
    } \
} while (0)
// Async 16B copy global->shared (LDGSTS). Register-free, deep MLP.
__device__ __forceinline__ void cp_async16(uint32_t dst, const void* src) {
    asm volatile("cp.async.cg.shared.global [%0], [%1], 16;"
        :: "r"(dst), "l"(src) : "memory");
}
#define CP_ASYNC_COMMIT() asm volatile("cp.async.commit_group;" ::: "memory")
#define CP_ASYNC_WAIT0()  asm volatile("cp.async.wait_group 0;" ::: "memory")
#define TCGEN05_LD_32X32B_X32(r, tmem_addr) \
    asm volatile( \
        "tcgen05.ld.sync.aligned.32x32b.x32.b32 " \
        "{%0, %1, %2, %3, %4, %5, %6, %7, " \
        " %8, %9, %10, %11, %12, %13, %14, %15, " \
        " %16, %17, %18, %19, %20, %21, %22, %23, " \
        " %24, %25, %26, %27, %28, %29, %30, %31}, [%32];" \
        : "=r"((r)[0]),  "=r"((r)[1]),  "=r"((r)[2]),  "=r"((r)[3]), \
          "=r"((r)[4]),  "=r"((r)[5]),  "=r"((r)[6]),  "=r"((r)[7]), \
          "=r"((r)[8]),  "=r"((r)[9]),  "=r"((r)[10]), "=r"((r)[11]), \
          "=r"((r)[12]), "=r"((r)[13]), "=r"((r)[14]), "=r"((r)[15]), \
          "=r"((r)[16]), "=r"((r)[17]), "=r"((r)[18]), "=r"((r)[19]), \
          "=r"((r)[20]), "=r"((r)[21]), "=r"((r)[22]), "=r"((r)[23]), \
          "=r"((r)[24]), "=r"((r)[25]), "=r"((r)[26]), "=r"((r)[27]), \
          "=r"((r)[28]), "=r"((r)[29]), "=r"((r)[30]), "=r"((r)[31]) \
        : "r"(tmem_addr))

// cg1 bf16 SS MMA (A in SMEM, B in SMEM), fp32 accumulate
__device__ __forceinline__ void mma_bf16_ss(uint32_t d, uint64_t a, uint64_t b,
                                            uint32_t idesc, bool en) {
    uint32_t e = en ? 1u : 0u;
    asm volatile(
        "{\n\t.reg .pred p;\n\t"
        "setp.ne.u32 p, %5, 0;\n\t"
        "tcgen05.mma.cta_group::1.kind::f16 [%0], %1, %2, %3, {%4, %4, %4, %4}, p;\n\t}"
        :: "r"(d), "l"(a), "l"(b), "r"(idesc), "r"(0u), "r"(e)
        : "memory");
}
#endif  // HAS_TCGEN05

// 64-bit SMEM descriptor: SW128, Blackwell v1, LBO=1, SBO=64 (K-major 128B rows)
static __device__ __forceinline__ uint64_t make_desc_sw128(uint32_t addr) {
    const uint64_t base =
        (uint64_t(2)  << 61) | (uint64_t(1) << 46) |
        (uint64_t(64) << 32) | (uint64_t(1) << 16);
    return base | ((uint64_t)(addr >> 4) & 0x3FFF);
}
#define SW128(bo) ((bo) ^ (((bo) >> 3) & 0x70))

// ================= scratch (device globals) ================================
__device__ __align__(16) float g_x  [BT*Cc];
__device__ __align__(16) float g_qkv[BT*QKVN];
// bf16 hi/lo activations
__device__ __align__(16) __nv_bfloat16 g_hh[BT*Cc],  g_hl[BT*Cc];
__device__ __align__(16) __nv_bfloat16 g_ah[BT*Cc],  g_al[BT*Cc];
__device__ __align__(16) __nv_bfloat16 g_fh[BT*DFF], g_fl[BT*DFF];
// transposed+split weights: [N(pad), K] K-major
__device__ __align__(16) __nv_bfloat16 g_qkvT_h[Ll*QKVN*Cc], g_qkvT_l[Ll*QKVN*Cc];
__device__ __align__(16) __nv_bfloat16 g_pT_h [Ll*Cc*Cc],    g_pT_l [Ll*Cc*Cc];
__device__ __align__(16) __nv_bfloat16 g_w1T_h[Ll*DFF*Cc],   g_w1T_l[Ll*DFF*Cc];
__device__ __align__(16) __nv_bfloat16 g_w2T_h[Ll*Cc*DFF],   g_w2T_l[Ll*Cc*DFF];
__device__ __align__(16) __nv_bfloat16 g_lmT_h[VPAD*Cc],     g_lmT_l[VPAD*Cc];

// ================= small kernels ===========================================
// Fused embedding + LN1(layer 0): one block per row. Writes x AND hh/hl.
__global__ void embed_ln_kernel(const int* __restrict__ idx,
                                const float* __restrict__ tok,
                                const float* __restrict__ pos,
                                const float* __restrict__ g,
                                const float* __restrict__ b,
                                float* __restrict__ x,
                                __nv_bfloat16* __restrict__ oh,
                                __nv_bfloat16* __restrict__ ol) {
    int row = blockIdx.x;
    int tid = threadIdx.x;
    int t   = row & (Tt - 1);
    float v = tok[idx[row] * Cc + tid] + pos[t * Cc + tid];
    x[row * Cc + tid] = v;
    float s = v, s2 = v * v;
    #pragma unroll
    for (int off = 16; off > 0; off >>= 1) {
        s  += __shfl_xor_sync(0xffffffffu, s,  off);
        s2 += __shfl_xor_sync(0xffffffffu, s2, off);
    }
    __shared__ float ss[8], ss2[8];
    __shared__ float mean_s, rstd_s;
    int w = tid >> 5, l = tid & 31;
    if (l == 0) { ss[w] = s; ss2[w] = s2; }
    __syncthreads();
    if (tid == 0) {
        float S = 0.f, S2 = 0.f;
        #pragma unroll
        for (int i = 0; i < 8; i++) { S += ss[i]; S2 += ss2[i]; }
        float m   = S * (1.0f / Cc);
        float var = S2 * (1.0f / Cc) - m * m;
        mean_s = m;
        rstd_s = rsqrtf(var + 1e-5f);
    }
    __syncthreads();
    float y = (v - mean_s) * rstd_s * g[tid] + b[tid];
    __nv_bfloat16 hi = __float2bfloat16(y);
    oh[row * Cc + tid] = hi;
    ol[row * Cc + tid] = __float2bfloat16(y - __bfloat162float(hi));
}

// generic: W [K,N] fp32 (layer-strided) -> out [Npad,K] bf16 hi/lo
__global__ void transpose_split_g(const float* __restrict__ W,
                                  __nv_bfloat16* __restrict__ oh,
                                  __nv_bfloat16* __restrict__ ol,
                                  int K, int N,
                                  size_t wstride, size_t ostride) {
    __shared__ float t[32][33];
    int l  = blockIdx.z;
    W  += (size_t)l * wstride;
    oh += (size_t)l * ostride;
    ol += (size_t)l * ostride;
    int n0 = blockIdx.x * 32, k0 = blockIdx.y * 32;
    int tx = threadIdx.x, ty = threadIdx.y;
    #pragma unroll
    for (int i = 0; i < 4; i++) {
        int k = k0 + ty + i * 8;
        int n = n0 + tx;
        t[ty + i * 8][tx] = (n < N) ? W[(size_t)k * N + n] : 0.f;
    }
    __syncthreads();
    #pragma unroll
    for (int i = 0; i < 4; i++) {
        int n = n0 + ty + i * 8;
        int k = k0 + tx;
        float v = t[tx][ty + i * 8];
        __nv_bfloat16 hi = __float2bfloat16(v);
        oh[(size_t)n * K + k] = hi;
        ol[(size_t)n * K + k] = __float2bfloat16(v - __bfloat162float(hi));
    }
}

// fused QKV transpose: wq/wk/wv [L][256][256] -> out [L][768][256]
__global__ void qkv_transpose(const float* __restrict__ wq,
                              const float* __restrict__ wk,
                              const float* __restrict__ wv,
                              __nv_bfloat16* __restrict__ oh,
                              __nv_bfloat16* __restrict__ ol) {
    __shared__ float t[32][33];
    int l  = blockIdx.z;
    int n0 = blockIdx.x * 32, k0 = blockIdx.y * 32;
    const float* W;
    int nb;
    if      (n0 < 256) { W = wq + (size_t)l * Cc * Cc; nb = n0; }
    else if (n0 < 512) { W = wk + (size_t)l * Cc * Cc; nb = n0 - 256; }
    else               { W = wv + (size_t)l * Cc * Cc; nb = n0 - 512; }
    oh += (size_t)l * QKVN * Cc;
    ol += (size_t)l * QKVN * Cc;
    int tx = threadIdx.x, ty = threadIdx.y;
    #pragma unroll
    for (int i = 0; i < 4; i++) {
        int k = k0 + ty + i * 8;
        t[ty + i * 8][tx] = W[(size_t)k * Cc + nb + tx];
    }
    __syncthreads();
    #pragma unroll
    for (int i = 0; i < 4; i++) {
        int n = n0 + ty + i * 8;
        int k = k0 + tx;
        float v = t[tx][ty + i * 8];
        __nv_bfloat16 hi = __float2bfloat16(v);
        oh[(size_t)n * Cc + k] = hi;
        ol[(size_t)n * Cc + k] = __float2bfloat16(v - __bfloat162float(hi));
    }
}

// LayerNorm, outputs bf16 hi/lo split
__global__ void ln_split_kernel(const float* __restrict__ x,
                                const float* __restrict__ g,
                                const float* __restrict__ b,
                                __nv_bfloat16* __restrict__ oh,
                                __nv_bfloat16* __restrict__ ol) {
    int row = blockIdx.x;
    int tid = threadIdx.x;
    float v = x[row * Cc + tid];
    float s = v, s2 = v * v;
    #pragma unroll
    for (int off = 16; off > 0; off >>= 1) {
        s  += __shfl_xor_sync(0xffffffffu, s,  off);
        s2 += __shfl_xor_sync(0xffffffffu, s2, off);
    }
    __shared__ float ss[8], ss2[8];
    __shared__ float mean_s, rstd_s;
    int w = tid >> 5, l = tid & 31;
    if (l == 0) { ss[w] = s; ss2[w] = s2; }
    __syncthreads();
    if (tid == 0) {
        float S = 0.f, S2 = 0.f;
        #pragma unroll
        for (int i = 0; i < 8; i++) { S += ss[i]; S2 += ss2[i]; }
        float m   = S * (1.0f / Cc);
        float var = S2 * (1.0f / Cc) - m * m;
        mean_s = m;
        rstd_s = rsqrtf(var + 1e-5f);
    }
    __syncthreads();
    float y = (v - mean_s) * rstd_s * g[tid] + b[tid];
    __nv_bfloat16 hi = __float2bfloat16(y);
    oh[row * Cc + tid] = hi;
    ol[row * Cc + tid] = __float2bfloat16(y - __bfloat162float(hi));
}

// ================= tcgen05 GEMM (cp.async loads, coalesced epilogue) ========
// Identical to R8/R9 (the winners) — protect the win.
#define GSM_TPTR 0
#define GSM_MBAR 8
#define GSM_AH   1024
#define GSM_AL   (1024 + 16384)
#define GSM_BH   (1024 + 32768)
#define GSM_BL   (1024 + 49152)
#define EPI_PAD  132                       // fp32 row pitch (16B-aligned rows)
#define GSM_SIZE (1024 + 128*EPI_PAD*4)    // 68608 >= 1024+65536 operand area
#define GEMM_IDESC 0x8200490u   // f32 acc, bf16 a/b, N=128, M=128

template<bool BIAS, bool RELU, bool RESID, bool SPLIT>
__global__ __launch_bounds__(256)
void tc_gemm(const __nv_bfloat16* __restrict__ Ah, const __nv_bfloat16* __restrict__ Al,
             const __nv_bfloat16* __restrict__ Bh, const __nv_bfloat16* __restrict__ Bl,
             const float* __restrict__ bias, const float* __restrict__ res,
             float* __restrict__ outf,
             __nv_bfloat16* __restrict__ oh, __nv_bfloat16* __restrict__ ol,
             int Nstore, int K, int ntiles, int Npad) {
#if HAS_TCGEN05
    extern __shared__ char smem[];
    const uint32_t smem_base = smem_to_u32(smem);
    const int tid  = threadIdx.x;
    const int wid  = tid >> 5;
    const int lane = tid & 31;
    const int bm   = blockIdx.y * 128;
    const int bn0  = blockIdx.x * 128 * ntiles;

    if (wid == 0) {
        TCGEN05_ALLOC(smem_base + GSM_TPTR, 128);
        TCGEN05_RELINQ();
    }
    if (tid == 0) MBARRIER_INIT(smem_base + GSM_MBAR, 1);
    __syncthreads();
    uint32_t tmem;
    asm volatile("ld.shared.b32 %0, [%1];" : "=r"(tmem) : "r"(smem_base + GSM_TPTR));

    const uint64_t dAh = make_desc_sw128(smem_base + GSM_AH);
    const uint64_t dAl = make_desc_sw128(smem_base + GSM_AL);
    const uint64_t dBh = make_desc_sw128(smem_base + GSM_BH);
    const uint64_t dBl = make_desc_sw128(smem_base + GSM_BL);

    // per-thread load mapping: 4 iters x one 16B vector per tile buffer
    const int lr = tid >> 3;            // row base 0..31 (+32*i)
    const int lb = (tid & 7) * 16;      // byte offset in 128B row

    const int nchunks = K >> 6;   // K/64
    int cc = 0;                   // global chunk counter (mbarrier parity)

    for (int t = 0; t < ntiles; t++) {
        const int bn = bn0 + t * 128;
        if (bn >= Npad) break;

        for (int c = 0; c < nchunks; c++) {
            const int k0 = c << 6;
            #pragma unroll
            for (int i = 0; i < 4; i++) {
                int r = lr + i * 32;
                uint32_t so = SW128(r * 128 + lb);
                const char* sa = (const char*)(Ah + (size_t)(bm + r) * K + k0) + lb;
                const char* sb = (const char*)(Al + (size_t)(bm + r) * K + k0) + lb;
                const char* sc = (const char*)(Bh + (size_t)(bn + r) * K + k0) + lb;
                const char* sd = (const char*)(Bl + (size_t)(bn + r) * K + k0) + lb;
                cp_async16(smem_base + GSM_AH + so, sa);
                cp_async16(smem_base + GSM_AL + so, sb);
                cp_async16(smem_base + GSM_BH + so, sc);
                cp_async16(smem_base + GSM_BL + so, sd);
            }
            CP_ASYNC_COMMIT();
            CP_ASYNC_WAIT0();
            FENCE_PROXY_ASYNC_SHARED_CTA();
            __syncthreads();

            if (wid == 0 && elect_one_pred()) {
                #pragma unroll
                for (int ks = 0; ks < 4; ks++) {
                    uint64_t oa = (uint64_t)(ks * 2);
                    mma_bf16_ss(tmem, dAh + oa, dBh + oa, GEMM_IDESC, !(c == 0 && ks == 0));
                    mma_bf16_ss(tmem, dAh + oa, dBl + oa, GEMM_IDESC, true);
                    mma_bf16_ss(tmem, dAl + oa, dBh + oa, GEMM_IDESC, true);
                }
                TCGEN05_COMMIT(smem_base + GSM_MBAR);
            }
            // warp 0 polls (no sleep), everyone else joins at the barrier
            if (wid == 0) MBARRIER_POLL(smem_base + GSM_MBAR, cc & 1);
            __syncthreads();
            cc++;
        }
        TCGEN05_FENCE_AFTER();

        // ---- epilogue: transpose through smem, fully coalesced stores ----
        {
            float* eps = (float*)(smem + GSM_AH);   // reuse operand smem
            const int wp   = wid & 3;
            const int colg = (wid >> 2) * 64;
            const int ml   = wp * 32 + lane;        // local row (m)
            #pragma unroll
            for (int half = 0; half < 2; half++) {
                int cb = colg + half * 32;
                uint32_t r[32];
                TCGEN05_LD_32X32B_X32(r, tmem + cb);
                TCGEN05_WAIT_LD();
                #pragma unroll
                for (int j = 0; j < 32; j++)
                    eps[ml * EPI_PAD + cb + j] = __uint_as_float(r[j]);
            }
            TCGEN05_FENCE_BEFORE();
            __syncthreads();

            // 128 rows x 32 float4-cols = 4096 quads; 256 threads x 16 iters.
            #pragma unroll 4
            for (int it = 0; it < 16; it++) {
                int q   = it * 256 + tid;
                int row = q >> 5;
                int c4  = (q & 31) << 2;
                int n   = bn + c4;
                if (n < Nstore) {
                    float4 v = *(const float4*)&eps[row * EPI_PAD + c4];
                    float vals[4] = {v.x, v.y, v.z, v.w};
                    size_t base = (size_t)(bm + row) * Nstore + n;
                    #pragma unroll
                    for (int e = 0; e < 4; e++) {
                        if (BIAS) vals[e] += bias[n + e];
                        if (RELU) vals[e] = fmaxf(vals[e], 0.f);
                    }
                    if (SPLIT) {
                        #pragma unroll
                        for (int e = 0; e < 4; e++) {
                            __nv_bfloat16 hi = __float2bfloat16(vals[e]);
                            oh[base + e] = hi;
                            ol[base + e] = __float2bfloat16(vals[e] - __bfloat162float(hi));
                        }
                    } else {
                        if (RESID) {
                            float4 rv = *(const float4*)&res[base];
                            vals[0] += rv.x; vals[1] += rv.y;
                            vals[2] += rv.z; vals[3] += rv.w;
                        }
                        float4 o;
                        o.x = vals[0]; o.y = vals[1]; o.z = vals[2]; o.w = vals[3];
                        *(float4*)&outf[base] = o;
                    }
                }
            }
            __syncthreads();   // eps dead before next tile's operand loads
        }
    }

    if (tid == 0) MBARRIER_INVAL(smem_base + GSM_MBAR);
    __syncthreads();
    if (wid == 0) TCGEN05_DEALLOC(tmem, 128);
#endif  // HAS_TCGEN05
}

// ================= fused causal attention (4-row batched, vectorized) =======
// smem: Kst[64][128] + Vs[128][68] + qs[8][4][64] + ps[8][4][128]
// Each warp processes 4 q-rows per pass: one K/V smem read feeds 4 rows of
// FMAs, and K reads are LDS.128 (lane owns keys 4*lane+e) / V reads LDS.64
// (lane owns dims 2*lane, 2*lane+1).
#define ATTN_SMEM ((64*128 + 128*68 + 8*4*64 + 8*4*128) * 4)   // 92160 B

__global__ __launch_bounds__(256)
void attn_kernel(const float* __restrict__ qkv,
                 __nv_bfloat16* __restrict__ oh, __nv_bfloat16* __restrict__ ol) {
    extern __shared__ float sm[];
    float* Kst = sm;                                 // [64][128] d-major
    float* Vs  = sm + 64 * 128;                      // [128][68]
    float* qs  = sm + 64 * 128 + 128 * 68;           // [8][4][64]
    float* ps  = qs + 8 * 4 * 64;                    // [8][4][128]

    const int b    = blockIdx.x >> 2;
    const int h    = blockIdx.x & 3;
    const int tid  = threadIdx.x;                    // 0..255
    const int lane = tid & 31;
    const int w    = tid >> 5;                       // 0..7

    const float* base_bt = qkv + (size_t)(b * Tt) * QKVN + h * HS;

    // Load K (transposed) and V: thread pair (row = tid>>1) covers one row.
    {
        const int row   = tid >> 1;
        const int dhalf = (tid & 1) * 32;
        const float* krow = base_bt + 256 + (size_t)row * QKVN + dhalf;
        const float* vrow = base_bt + 512 + (size_t)row * QKVN + dhalf;
        #pragma unroll
        for (int d4 = 0; d4 < 8; d4++) {
            int d = dhalf + d4 * 4;
            float4 kv = *(const float4*)(krow + d4 * 4);
            Kst[(d + 0) * 128 + row] = kv.x;
            Kst[(d + 1) * 128 + row] = kv.y;
            Kst[(d + 2) * 128 + row] = kv.z;
            Kst[(d + 3) * 128 + row] = kv.w;
            *(float4*)&Vs[row * 68 + d] = *(const float4*)(vrow + d4 * 4);
        }
    }
    __syncthreads();

    const float scale = 0.0625f;  // 256^-0.5
    float* qw = qs + w * 4 * 64;
    float* pw = ps + w * 4 * 128;

    for (int batch = 0; batch < 4; batch++) {
        int qr[4];
        #pragma unroll
        for (int i = 0; i < 4; i++) qr[i] = (batch * 4 + i) * 8 + w;

        // stage 4 q rows
        #pragma unroll
        for (int i = 0; i < 4; i++) {
            const float* qrow = base_bt + (size_t)qr[i] * QKVN;
            qw[i * 64 + lane]      = qrow[lane];
            qw[i * 64 + lane + 32] = qrow[lane + 32];
        }
        __syncwarp();

        // scores: s[i][e] for key kk = 4*lane + e
        float s[4][4];
        #pragma unroll
        for (int i = 0; i < 4; i++)
            #pragma unroll
            for (int e = 0; e < 4; e++) s[i][e] = 0.f;

        #pragma unroll 8
        for (int d = 0; d < 64; d++) {
            float4 kv = *(const float4*)&Kst[d * 128 + 4 * lane];
            float q0 = qw[0 * 64 + d];
            float q1 = qw[1 * 64 + d];
            float q2 = qw[2 * 64 + d];
            float q3 = qw[3 * 64 + d];
            s[0][0] = fmaf(q0, kv.x, s[0][0]); s[0][1] = fmaf(q0, kv.y, s[0][1]);
            s[0][2] = fmaf(q0, kv.z, s[0][2]); s[0][3] = fmaf(q0, kv.w, s[0][3]);
            s[1][0] = fmaf(q1, kv.x, s[1][0]); s[1][1] = fmaf(q1, kv.y, s[1][1]);
            s[1][2] = fmaf(q1, kv.z, s[1][2]); s[1][3] = fmaf(q1, kv.w, s[1][3]);
            s[2][0] = fmaf(q2, kv.x, s[2][0]); s[2][1] = fmaf(q2, kv.y, s[2][1]);
            s[2][2] = fmaf(q2, kv.z, s[2][2]); s[2][3] = fmaf(q2, kv.w, s[2][3]);
            s[3][0] = fmaf(q3, kv.x, s[3][0]); s[3][1] = fmaf(q3, kv.y, s[3][1]);
            s[3][2] = fmaf(q3, kv.z, s[3][2]); s[3][3] = fmaf(q3, kv.w, s[3][3]);
        }

        // softmax per row, store p (zeros for masked keys) as one STS.128
        #pragma unroll
        for (int i = 0; i < 4; i++) {
            float e[4];
            float mx = -1e30f;
            #pragma unroll
            for (int ee = 0; ee < 4; ee++) {
                int kk = 4 * lane + ee;
                float sv = s[i][ee] * scale;
                s[i][ee] = sv;
                if (kk <= qr[i]) mx = fmaxf(mx, sv);
            }
            #pragma unroll
            for (int off = 16; off > 0; off >>= 1)
                mx = fmaxf(mx, __shfl_xor_sync(0xffffffffu, mx, off));
            float sum = 0.f;
            #pragma unroll
            for (int ee = 0; ee < 4; ee++) {
                int kk = 4 * lane + ee;
                e[ee] = (kk <= qr[i]) ? __expf(s[i][ee] - mx) : 0.f;
                sum += e[ee];
            }
            #pragma unroll
            for (int off = 16; off > 0; off >>= 1)
                sum += __shfl_xor_sync(0xffffffffu, sum, off);
            float rs = 1.0f / sum;
            float4 pv;
            pv.x = e[0] * rs; pv.y = e[1] * rs;
            pv.z = e[2] * rs; pv.w = e[3] * rs;
            *(float4*)&pw[i * 128 + 4 * lane] = pv;
        }
        __syncwarp();

        // PV: lane owns dims d0 = 2*lane, d1 = 2*lane+1
        float o[4][2];
        #pragma unroll
        for (int i = 0; i < 4; i++) { o[i][0] = 0.f; o[i][1] = 0.f; }
        const int kmax = qr[3];   // largest row in batch; masked p are 0
        #pragma unroll 4
        for (int kk = 0; kk <= kmax; kk++) {
            float2 v = *(const float2*)&Vs[kk * 68 + 2 * lane];
            float p0 = pw[0 * 128 + kk];
            float p1 = pw[1 * 128 + kk];
            float p2 = pw[2 * 128 + kk];
            float p3 = pw[3 * 128 + kk];
            o[0][0] = fmaf(p0, v.x, o[0][0]); o[0][1] = fmaf(p0, v.y, o[0][1]);
            o[1][0] = fmaf(p1, v.x, o[1][0]); o[1][1] = fmaf(p1, v.y, o[1][1]);
            o[2][0] = fmaf(p2, v.x, o[2][0]); o[2][1] = fmaf(p2, v.y, o[2][1]);
            o[3][0] = fmaf(p3, v.x, o[3][0]); o[3][1] = fmaf(p3, v.y, o[3][1]);
        }

        #pragma unroll
        for (int i = 0; i < 4; i++) {
            size_t obase = (size_t)(b * Tt + qr[i]) * Cc + h * HS + 2 * lane;
            __nv_bfloat16 h0 = __float2bfloat16(o[i][0]);
            __nv_bfloat16 h1 = __float2bfloat16(o[i][1]);
            oh[obase]     = h0;
            oh[obase + 1] = h1;
            ol[obase]     = __float2bfloat16(o[i][0] - __bfloat162float(h0));
            ol[obase + 1] = __float2bfloat16(o[i][1] - __bfloat162float(h1));
        }
        __syncwarp();   // qw/pw reused next batch
    }
}

// ================= launch ===================================================
extern "C" void kernel_launch(void* const* d_in, const int* in_sizes, int n_in,
                              void* d_out, int out_size) {
    const int*   idx   = (const int*)  d_in[0];
    const float* tok   = (const float*)d_in[1];
    const float* pos   = (const float*)d_in[2];
    const float* ln1g  = (const float*)d_in[3];
    const float* ln1b  = (const float*)d_in[4];
    const float* wq    = (const float*)d_in[5];
    const float* wk    = (const float*)d_in[6];
    const float* wv    = (const float*)d_in[7];
    const float* projw = (const float*)d_in[8];
    const float* projb = (const float*)d_in[9];
    const float* ln2g  = (const float*)d_in[10];
    const float* ln2b  = (const float*)d_in[11];
    const float* w1    = (const float*)d_in[12];
    const float* b1    = (const float*)d_in[13];
    const float* w2    = (const float*)d_in[14];
    const float* b2    = (const float*)d_in[15];
    const float* lnfg  = (const float*)d_in[16];
    const float* lnfb  = (const float*)d_in[17];
    const float* lmw   = (const float*)d_in[18];
    const float* lmb   = (const float*)d_in[19];
    float* out = (float*)d_out;

    float *x, *qkv;
    __nv_bfloat16 *hh, *hl, *ah, *al, *fh, *fl;
    __nv_bfloat16 *qkvTh, *qkvTl, *pTh, *pTl;
    __nv_bfloat16 *w1Th, *w1Tl, *w2Th, *w2Tl, *lmTh, *lmTl;
    cudaGetSymbolAddress((void**)&x,   g_x);
    cudaGetSymbolAddress((void**)&qkv, g_qkv);
    cudaGetSymbolAddress((void**)&hh, g_hh);  cudaGetSymbolAddress((void**)&hl, g_hl);
    cudaGetSymbolAddress((void**)&ah, g_ah);  cudaGetSymbolAddress((void**)&al, g_al);
    cudaGetSymbolAddress((void**)&fh, g_fh);  cudaGetSymbolAddress((void**)&fl, g_fl);
    cudaGetSymbolAddress((void**)&qkvTh, g_qkvT_h); cudaGetSymbolAddress((void**)&qkvTl, g_qkvT_l);
    cudaGetSymbolAddress((void**)&pTh,  g_pT_h);    cudaGetSymbolAddress((void**)&pTl,  g_pT_l);
    cudaGetSymbolAddress((void**)&w1Th, g_w1T_h);   cudaGetSymbolAddress((void**)&w1Tl, g_w1T_l);
    cudaGetSymbolAddress((void**)&w2Th, g_w2T_h);   cudaGetSymbolAddress((void**)&w2Tl, g_w2T_l);
    cudaGetSymbolAddress((void**)&lmTh, g_lmT_h);   cudaGetSymbolAddress((void**)&lmTl, g_lmT_l);

    cudaFuncSetAttribute(attn_kernel,
                         cudaFuncAttributeMaxDynamicSharedMemorySize, ATTN_SMEM);
    cudaFuncSetAttribute(tc_gemm<false,false,false,false>,
                         cudaFuncAttributeMaxDynamicSharedMemorySize, GSM_SIZE);
    cudaFuncSetAttribute(tc_gemm<true,false,true,false>,
                         cudaFuncAttributeMaxDynamicSharedMemorySize, GSM_SIZE);
    cudaFuncSetAttribute(tc_gemm<true,true,false,true>,
                         cudaFuncAttributeMaxDynamicSharedMemorySize, GSM_SIZE);
    cudaFuncSetAttribute(tc_gemm<true,false,false,false>,
                         cudaFuncAttributeMaxDynamicSharedMemorySize, GSM_SIZE);

    dim3 tb(32, 8);
    const dim3 gC(Cc / 128,   BT / 128);   // N=256
    const dim3 gQ(QKVN / 128, BT / 128);   // N=768
    const dim3 gF(DFF / 128,  BT / 128);   // N=1024
    const dim3 gV(VPAD / 512, BT / 128);   // LM head: 20 x 128, 4 N-tiles/CTA

    // Launch order: index 3 is the profiled launch -> attn_kernel.
    qkv_transpose<<<dim3(QKVN/32, Cc/32, Ll), tb>>>(wq, wk, wv, qkvTh, qkvTl);      // 0
    embed_ln_kernel<<<BT, 256>>>(idx, tok, pos, ln1g, ln1b, x, hh, hl);             // 1
    tc_gemm<false,false,false,false><<<gQ, 256, GSM_SIZE>>>(                        // 2
        hh, hl, qkvTh, qkvTl, nullptr, nullptr, qkv, nullptr, nullptr,
        QKVN, Cc, 1, QKVN);
    attn_kernel<<<Bb * Hh, 256, ATTN_SMEM>>>(qkv, ah, al);                          // 3 (PROFILED)
    transpose_split_g<<<dim3(Cc/32, Cc/32, Ll), tb>>>(projw, pTh, pTl, Cc, Cc,
                                                      (size_t)Cc*Cc, (size_t)Cc*Cc);
    transpose_split_g<<<dim3(DFF/32, Cc/32, Ll), tb>>>(w1, w1Th, w1Tl, Cc, DFF,
                                                       (size_t)Cc*DFF, (size_t)Cc*DFF);
    transpose_split_g<<<dim3(Cc/32, DFF/32, Ll), tb>>>(w2, w2Th, w2Tl, DFF, Cc,
                                                       (size_t)Cc*DFF, (size_t)Cc*DFF);
    transpose_split_g<<<dim3(VPAD/32, Cc/32, 1), tb>>>(lmw, lmTh, lmTl, Cc, Vv, 0, 0);

    for (int l = 0; l < Ll; l++) {
        size_t oQ = (size_t)l * QKVN * Cc;
        size_t o2 = (size_t)l * Cc * Cc;
        size_t oF = (size_t)l * Cc * DFF;

        if (l > 0) {
            ln_split_kernel<<<BT, 256>>>(x, ln1g + l*Cc, ln1b + l*Cc, hh, hl);
            tc_gemm<false,false,false,false><<<gQ, 256, GSM_SIZE>>>(
                hh, hl, qkvTh + oQ, qkvTl + oQ, nullptr, nullptr, qkv,
                nullptr, nullptr, QKVN, Cc, 1, QKVN);
            attn_kernel<<<Bb * Hh, 256, ATTN_SMEM>>>(qkv, ah, al);
        }

        tc_gemm<true,false,true,false><<<gC, 256, GSM_SIZE>>>(
            ah, al, pTh + o2, pTl + o2, projb + l*Cc, x, x, nullptr, nullptr,
            Cc, Cc, 1, Cc);

        ln_split_kernel<<<BT, 256>>>(x, ln2g + l*Cc, ln2b + l*Cc, hh, hl);

        tc_gemm<true,true,false,true><<<gF, 256, GSM_SIZE>>>(
            hh, hl, w1Th + oF, w1Tl + oF, b1 + l*DFF, nullptr, nullptr, fh, fl,
            DFF, Cc, 1, DFF);

        tc_gemm<true,false,true,false><<<gC, 256, GSM_SIZE>>>(
            fh, fl, w2Th + oF, w2Tl + oF, b2 + l*Cc, x, x, nullptr, nullptr,
            Cc, DFF, 1, Cc);
    }

    ln_split_kernel<<<BT, 256>>>(x, lnfg, lnfb, hh, hl);

    tc_gemm<true,false,false,false><<<gV, 256, GSM_SIZE>>>(
        hh, hl, lmTh, lmTl, lmb, nullptr, out, nullptr, nullptr,
        Vv, Cc, 4, VPAD);
}

// round 11
// speedup vs baseline: 3.8146x; 1.0044x over previous
#include <cuda_runtime.h>
#include <cuda_bf16.h>
#include <math.h>
#include <cstdint>

// tcgen05 is only legal on arch-specific targets (sm_103a / sm_100a).
// The harness's nvcc also runs a generic compute_103 PTX pass; guard so that
// pass compiles empty bodies (the sm_103a cubin is what actually runs).
#if !defined(__CUDA_ARCH__) || defined(__CUDA_ARCH_FEAT_SM103_ALL) || \
    defined(__CUDA_ARCH_FEAT_SM100_ALL) || defined(__CUDA_ARCH_FEAT_SM101_ALL)
#define HAS_TCGEN05 1
#else
#define HAS_TCGEN05 0
#endif

// Problem dims
#define Bb   128
#define Tt   128
#define Cc   256
#define Hh   4
#define HS   64
#define Ll   6
#define DFF  1024
#define Vv   10000
#define BT   (Bb*Tt)   // 16384
#define VPAD 10240     // 80*128 (LM head padded to 4-tile groups)
#define QKVN 768

// ================= PTX helpers (sm_103a tcgen05) ===========================
__device__ __forceinline__ uint32_t smem_to_u32(const void* p) {
    uint32_t a;
    asm("{ .reg .u64 t; cvta.to.shared.u64 t, %1; cvt.u32.u64 %0, t; }"
        : "=r"(a) : "l"(p));
    return a;
}

#if HAS_TCGEN05
__device__ __forceinline__ uint32_t elect_one_pred() {
    uint32_t pred;
    asm volatile(
        "{\n\t.reg .pred p;\n\telect.sync _|p, 0xFFFFFFFF;\n\t"
        "selp.b32 %0, 1, 0, p;\n\t}"
        : "=r"(pred));
    return pred;
}
#define TCGEN05_ALLOC(smem_addr, nCols) \
    asm volatile("tcgen05.alloc.cta_group::1.sync.aligned.shared::cta.b32 [%0], %1;" \
        :: "r"((uint32_t)(smem_addr)), "r"((uint32_t)(nCols)) : "memory")
#define TCGEN05_DEALLOC(tmem_addr, nCols) \
    asm volatile("tcgen05.dealloc.cta_group::1.sync.aligned.b32 %0, %1;" \
        :: "r"(tmem_addr), "r"((uint32_t)(nCols)))
#define TCGEN05_RELINQ() \
    asm volatile("tcgen05.relinquish_alloc_permit.cta_group::1.sync.aligned;")
#define TCGEN05_COMMIT(mbar) \
    asm volatile("tcgen05.commit.cta_group::1.mbarrier::arrive::one.shared::cluster.b64 [%0];" \
        :: "r"((uint32_t)(mbar)) : "memory")
#define TCGEN05_FENCE_BEFORE() \
    asm volatile("tcgen05.fence::before_thread_sync;" ::: "memory")
#define TCGEN05_FENCE_AFTER() \
    asm volatile("tcgen05.fence::after_thread_sync;" ::: "memory")
#define TCGEN05_WAIT_LD() \
    asm volatile("tcgen05.wait::ld.sync.aligned;" ::: "memory")
#define FENCE_PROXY_ASYNC_SHARED_CTA() \
    asm volatile("fence.proxy.async.shared::cta;" ::: "memory")
#define MBARRIER_INIT(mbar, count) \
    asm volatile("mbarrier.init.shared.b64 [%0], %1;" \
        :: "r"((uint32_t)(mbar)), "r"((uint32_t)(count)) : "memory")
#define MBARRIER_INVAL(mbar) \
    asm volatile("mbarrier.inval.shared.b64 [%0];" :: "r"((uint32_t)(mbar)) : "memory")
// Non-blocking poll: mbarrier.test_wait in a spin loop, no sleep.
#define MBARRIER_POLL(mbar, parity) do { \
    uint32_t _mbar = (uint32_t)(mbar); \
    uint32_t _par  = (uint32_t)(parity); \
    uint32_t _done = 0; \
    while (!_done) { \
        asm volatile( \
            "{\n\t.reg .pred p;\n\t" \
            "mbarrier.test_wait.parity.acquire.cta.shared::cta.b64 p, [%1], %2;\n\t" \
            "selp.b32 %0, 1, 0, p;\n\t}" \
            : "=r"(_done) : "r"(_mbar), "r"(_par) : "memory"); \
    } \
} while (0)
// Async 16B copy global->shared (LDGSTS). Register-free, deep MLP.
__device__ __forceinline__ void cp_async16(uint32_t dst, const void* src) {
    asm volatile("cp.async.cg.shared.global [%0], [%1], 16;"
        :: "r"(dst), "l"(src) : "memory");
}
#define CP_ASYNC_COMMIT() asm volatile("cp.async.commit_group;" ::: "memory")
#define CP_ASYNC_WAIT0()  asm volatile("cp.async.wait_group 0;" ::: "memory")
#define TCGEN05_LD_32X32B_X32(r, tmem_addr) \
    asm volatile( \
        "tcgen05.ld.sync.aligned.32x32b.x32.b32 " \
        "{%0, %1, %2, %3, %4, %5, %6, %7, " \
        " %8, %9, %10, %11, %12, %13, %14, %15, " \
        " %16, %17, %18, %19, %20, %21, %22, %23, " \
        " %24, %25, %26, %27, %28, %29, %30, %31}, [%32];" \
        : "=r"((r)[0]),  "=r"((r)[1]),  "=r"((r)[2]),  "=r"((r)[3]), \
          "=r"((r)[4]),  "=r"((r)[5]),  "=r"((r)[6]),  "=r"((r)[7]), \
          "=r"((r)[8]),  "=r"((r)[9]),  "=r"((r)[10]), "=r"((r)[11]), \
          "=r"((r)[12]), "=r"((r)[13]), "=r"((r)[14]), "=r"((r)[15]), \
          "=r"((r)[16]), "=r"((r)[17]), "=r"((r)[18]), "=r"((r)[19]), \
          "=r"((r)[20]), "=r"((r)[21]), "=r"((r)[22]), "=r"((r)[23]), \
          "=r"((r)[24]), "=r"((r)[25]), "=r"((r)[26]), "=r"((r)[27]), \
          "=r"((r)[28]), "=r"((r)[29]), "=r"((r)[30]), "=r"((r)[31]) \
        : "r"(tmem_addr))

// cg1 bf16 SS MMA (A in SMEM, B in SMEM), fp32 accumulate
__device__ __forceinline__ void mma_bf16_ss(uint32_t d, uint64_t a, uint64_t b,
                                            uint32_t idesc, bool en) {
    uint32_t e = en ? 1u : 0u;
    asm volatile(
        "{\n\t.reg .pred p;\n\t"
        "setp.ne.u32 p, %5, 0;\n\t"
        "tcgen05.mma.cta_group::1.kind::f16 [%0], %1, %2, %3, {%4, %4, %4, %4}, p;\n\t}"
        :: "r"(d), "l"(a), "l"(b), "r"(idesc), "r"(0u), "r"(e)
        : "memory");
}
#endif  // HAS_TCGEN05

// 64-bit SMEM descriptor: SW128, Blackwell v1, LBO=1, SBO=64 (K-major 128B rows)
static __device__ __forceinline__ uint64_t make_desc_sw128(uint32_t addr) {
    const uint64_t base =
        (uint64_t(2)  << 61) | (uint64_t(1) << 46) |
        (uint64_t(64) << 32) | (uint64_t(1) << 16);
    return base | ((uint64_t)(addr >> 4) & 0x3FFF);
}
#define SW128(bo) ((bo) ^ (((bo) >> 3) & 0x70))

// ================= scratch (device globals) ================================
__device__ __align__(16) float g_x  [BT*Cc];
__device__ __align__(16) float g_qkv[BT*QKVN];
// bf16 hi/lo activations
__device__ __align__(16) __nv_bfloat16 g_hh[BT*Cc],  g_hl[BT*Cc];
__device__ __align__(16) __nv_bfloat16 g_ah[BT*Cc],  g_al[BT*Cc];
__device__ __align__(16) __nv_bfloat16 g_fh[BT*DFF], g_fl[BT*DFF];
// transposed+split weights: [N(pad), K] K-major
__device__ __align__(16) __nv_bfloat16 g_qkvT_h[Ll*QKVN*Cc], g_qkvT_l[Ll*QKVN*Cc];
__device__ __align__(16) __nv_bfloat16 g_pT_h [Ll*Cc*Cc],    g_pT_l [Ll*Cc*Cc];
__device__ __align__(16) __nv_bfloat16 g_w1T_h[Ll*DFF*Cc],   g_w1T_l[Ll*DFF*Cc];
__device__ __align__(16) __nv_bfloat16 g_w2T_h[Ll*Cc*DFF],   g_w2T_l[Ll*Cc*DFF];
__device__ __align__(16) __nv_bfloat16 g_lmT_h[VPAD*Cc],     g_lmT_l[VPAD*Cc];

// ================= small kernels ===========================================
// Fused embedding + LN1(layer 0): one block per row. Writes x AND hh/hl.
__global__ void embed_ln_kernel(const int* __restrict__ idx,
                                const float* __restrict__ tok,
                                const float* __restrict__ pos,
                                const float* __restrict__ g,
                                const float* __restrict__ b,
                                float* __restrict__ x,
                                __nv_bfloat16* __restrict__ oh,
                                __nv_bfloat16* __restrict__ ol) {
    int row = blockIdx.x;
    int tid = threadIdx.x;
    int t   = row & (Tt - 1);
    float v = tok[idx[row] * Cc + tid] + pos[t * Cc + tid];
    x[row * Cc + tid] = v;
    float s = v, s2 = v * v;
    #pragma unroll
    for (int off = 16; off > 0; off >>= 1) {
        s  += __shfl_xor_sync(0xffffffffu, s,  off);
        s2 += __shfl_xor_sync(0xffffffffu, s2, off);
    }
    __shared__ float ss[8], ss2[8];
    __shared__ float mean_s, rstd_s;
    int w = tid >> 5, l = tid & 31;
    if (l == 0) { ss[w] = s; ss2[w] = s2; }
    __syncthreads();
    if (tid == 0) {
        float S = 0.f, S2 = 0.f;
        #pragma unroll
        for (int i = 0; i < 8; i++) { S += ss[i]; S2 += ss2[i]; }
        float m   = S * (1.0f / Cc);
        float var = S2 * (1.0f / Cc) - m * m;
        mean_s = m;
        rstd_s = rsqrtf(var + 1e-5f);
    }
    __syncthreads();
    float y = (v - mean_s) * rstd_s * g[tid] + b[tid];
    __nv_bfloat16 hi = __float2bfloat16(y);
    oh[row * Cc + tid] = hi;
    ol[row * Cc + tid] = __float2bfloat16(y - __bfloat162float(hi));
}

// generic: W [K,N] fp32 (layer-strided) -> out [Npad,K] bf16 hi/lo
__global__ void transpose_split_g(const float* __restrict__ W,
                                  __nv_bfloat16* __restrict__ oh,
                                  __nv_bfloat16* __restrict__ ol,
                                  int K, int N,
                                  size_t wstride, size_t ostride) {
    __shared__ float t[32][33];
    int l  = blockIdx.z;
    W  += (size_t)l * wstride;
    oh += (size_t)l * ostride;
    ol += (size_t)l * ostride;
    int n0 = blockIdx.x * 32, k0 = blockIdx.y * 32;
    int tx = threadIdx.x, ty = threadIdx.y;
    #pragma unroll
    for (int i = 0; i < 4; i++) {
        int k = k0 + ty + i * 8;
        int n = n0 + tx;
        t[ty + i * 8][tx] = (n < N) ? W[(size_t)k * N + n] : 0.f;
    }
    __syncthreads();
    #pragma unroll
    for (int i = 0; i < 4; i++) {
        int n = n0 + ty + i * 8;
        int k = k0 + tx;
        float v = t[tx][ty + i * 8];
        __nv_bfloat16 hi = __float2bfloat16(v);
        oh[(size_t)n * K + k] = hi;
        ol[(size_t)n * K + k] = __float2bfloat16(v - __bfloat162float(hi));
    }
}

// fused QKV transpose: wq/wk/wv [L][256][256] -> out [L][768][256]
__global__ void qkv_transpose(const float* __restrict__ wq,
                              const float* __restrict__ wk,
                              const float* __restrict__ wv,
                              __nv_bfloat16* __restrict__ oh,
                              __nv_bfloat16* __restrict__ ol) {
    __shared__ float t[32][33];
    int l  = blockIdx.z;
    int n0 = blockIdx.x * 32, k0 = blockIdx.y * 32;
    const float* W;
    int nb;
    if      (n0 < 256) { W = wq + (size_t)l * Cc * Cc; nb = n0; }
    else if (n0 < 512) { W = wk + (size_t)l * Cc * Cc; nb = n0 - 256; }
    else               { W = wv + (size_t)l * Cc * Cc; nb = n0 - 512; }
    oh += (size_t)l * QKVN * Cc;
    ol += (size_t)l * QKVN * Cc;
    int tx = threadIdx.x, ty = threadIdx.y;
    #pragma unroll
    for (int i = 0; i < 4; i++) {
        int k = k0 + ty + i * 8;
        t[ty + i * 8][tx] = W[(size_t)k * Cc + nb + tx];
    }
    __syncthreads();
    #pragma unroll
    for (int i = 0; i < 4; i++) {
        int n = n0 + ty + i * 8;
        int k = k0 + tx;
        float v = t[tx][ty + i * 8];
        __nv_bfloat16 hi = __float2bfloat16(v);
        oh[(size_t)n * Cc + k] = hi;
        ol[(size_t)n * Cc + k] = __float2bfloat16(v - __bfloat162float(hi));
    }
}

// LayerNorm, outputs bf16 hi/lo split
__global__ void ln_split_kernel(const float* __restrict__ x,
                                const float* __restrict__ g,
                                const float* __restrict__ b,
                                __nv_bfloat16* __restrict__ oh,
                                __nv_bfloat16* __restrict__ ol) {
    int row = blockIdx.x;
    int tid = threadIdx.x;
    float v = x[row * Cc + tid];
    float s = v, s2 = v * v;
    #pragma unroll
    for (int off = 16; off > 0; off >>= 1) {
        s  += __shfl_xor_sync(0xffffffffu, s,  off);
        s2 += __shfl_xor_sync(0xffffffffu, s2, off);
    }
    __shared__ float ss[8], ss2[8];
    __shared__ float mean_s, rstd_s;
    int w = tid >> 5, l = tid & 31;
    if (l == 0) { ss[w] = s; ss2[w] = s2; }
    __syncthreads();
    if (tid == 0) {
        float S = 0.f, S2 = 0.f;
        #pragma unroll
        for (int i = 0; i < 8; i++) { S += ss[i]; S2 += ss2[i]; }
        float m   = S * (1.0f / Cc);
        float var = S2 * (1.0f / Cc) - m * m;
        mean_s = m;
        rstd_s = rsqrtf(var + 1e-5f);
    }
    __syncthreads();
    float y = (v - mean_s) * rstd_s * g[tid] + b[tid];
    __nv_bfloat16 hi = __float2bfloat16(y);
    oh[row * Cc + tid] = hi;
    ol[row * Cc + tid] = __float2bfloat16(y - __bfloat162float(hi));
}

// ================= tcgen05 GEMM (cp.async loads, coalesced epilogue) ========
// Identical to R8-R10 (the winners) — protect the win.
#define GSM_TPTR 0
#define GSM_MBAR 8
#define GSM_AH   1024
#define GSM_AL   (1024 + 16384)
#define GSM_BH   (1024 + 32768)
#define GSM_BL   (1024 + 49152)
#define EPI_PAD  132                       // fp32 row pitch (16B-aligned rows)
#define GSM_SIZE (1024 + 128*EPI_PAD*4)    // 68608 >= 1024+65536 operand area
#define GEMM_IDESC 0x8200490u   // f32 acc, bf16 a/b, N=128, M=128

template<bool BIAS, bool RELU, bool RESID, bool SPLIT>
__global__ __launch_bounds__(256)
void tc_gemm(const __nv_bfloat16* __restrict__ Ah, const __nv_bfloat16* __restrict__ Al,
             const __nv_bfloat16* __restrict__ Bh, const __nv_bfloat16* __restrict__ Bl,
             const float* __restrict__ bias, const float* __restrict__ res,
             float* __restrict__ outf,
             __nv_bfloat16* __restrict__ oh, __nv_bfloat16* __restrict__ ol,
             int Nstore, int K, int ntiles, int Npad) {
#if HAS_TCGEN05
    extern __shared__ char smem[];
    const uint32_t smem_base = smem_to_u32(smem);
    const int tid  = threadIdx.x;
    const int wid  = tid >> 5;
    const int lane = tid & 31;
    const int bm   = blockIdx.y * 128;
    const int bn0  = blockIdx.x * 128 * ntiles;

    if (wid == 0) {
        TCGEN05_ALLOC(smem_base + GSM_TPTR, 128);
        TCGEN05_RELINQ();
    }
    if (tid == 0) MBARRIER_INIT(smem_base + GSM_MBAR, 1);
    __syncthreads();
    uint32_t tmem;
    asm volatile("ld.shared.b32 %0, [%1];" : "=r"(tmem) : "r"(smem_base + GSM_TPTR));

    const uint64_t dAh = make_desc_sw128(smem_base + GSM_AH);
    const uint64_t dAl = make_desc_sw128(smem_base + GSM_AL);
    const uint64_t dBh = make_desc_sw128(smem_base + GSM_BH);
    const uint64_t dBl = make_desc_sw128(smem_base + GSM_BL);

    // per-thread load mapping: 4 iters x one 16B vector per tile buffer
    const int lr = tid >> 3;            // row base 0..31 (+32*i)
    const int lb = (tid & 7) * 16;      // byte offset in 128B row

    const int nchunks = K >> 6;   // K/64
    int cc = 0;                   // global chunk counter (mbarrier parity)

    for (int t = 0; t < ntiles; t++) {
        const int bn = bn0 + t * 128;
        if (bn >= Npad) break;

        for (int c = 0; c < nchunks; c++) {
            const int k0 = c << 6;
            #pragma unroll
            for (int i = 0; i < 4; i++) {
                int r = lr + i * 32;
                uint32_t so = SW128(r * 128 + lb);
                const char* sa = (const char*)(Ah + (size_t)(bm + r) * K + k0) + lb;
                const char* sb = (const char*)(Al + (size_t)(bm + r) * K + k0) + lb;
                const char* sc = (const char*)(Bh + (size_t)(bn + r) * K + k0) + lb;
                const char* sd = (const char*)(Bl + (size_t)(bn + r) * K + k0) + lb;
                cp_async16(smem_base + GSM_AH + so, sa);
                cp_async16(smem_base + GSM_AL + so, sb);
                cp_async16(smem_base + GSM_BH + so, sc);
                cp_async16(smem_base + GSM_BL + so, sd);
            }
            CP_ASYNC_COMMIT();
            CP_ASYNC_WAIT0();
            FENCE_PROXY_ASYNC_SHARED_CTA();
            __syncthreads();

            if (wid == 0 && elect_one_pred()) {
                #pragma unroll
                for (int ks = 0; ks < 4; ks++) {
                    uint64_t oa = (uint64_t)(ks * 2);
                    mma_bf16_ss(tmem, dAh + oa, dBh + oa, GEMM_IDESC, !(c == 0 && ks == 0));
                    mma_bf16_ss(tmem, dAh + oa, dBl + oa, GEMM_IDESC, true);
                    mma_bf16_ss(tmem, dAl + oa, dBh + oa, GEMM_IDESC, true);
                }
                TCGEN05_COMMIT(smem_base + GSM_MBAR);
            }
            // warp 0 polls (no sleep), everyone else joins at the barrier
            if (wid == 0) MBARRIER_POLL(smem_base + GSM_MBAR, cc & 1);
            __syncthreads();
            cc++;
        }
        TCGEN05_FENCE_AFTER();

        // ---- epilogue: transpose through smem, fully coalesced stores ----
        {
            float* eps = (float*)(smem + GSM_AH);   // reuse operand smem
            const int wp   = wid & 3;
            const int colg = (wid >> 2) * 64;
            const int ml   = wp * 32 + lane;        // local row (m)
            #pragma unroll
            for (int half = 0; half < 2; half++) {
                int cb = colg + half * 32;
                uint32_t r[32];
                TCGEN05_LD_32X32B_X32(r, tmem + cb);
                TCGEN05_WAIT_LD();
                #pragma unroll
                for (int j = 0; j < 32; j++)
                    eps[ml * EPI_PAD + cb + j] = __uint_as_float(r[j]);
            }
            TCGEN05_FENCE_BEFORE();
            __syncthreads();

            // 128 rows x 32 float4-cols = 4096 quads; 256 threads x 16 iters.
            #pragma unroll 4
            for (int it = 0; it < 16; it++) {
                int q   = it * 256 + tid;
                int row = q >> 5;
                int c4  = (q & 31) << 2;
                int n   = bn + c4;
                if (n < Nstore) {
                    float4 v = *(const float4*)&eps[row * EPI_PAD + c4];
                    float vals[4] = {v.x, v.y, v.z, v.w};
                    size_t base = (size_t)(bm + row) * Nstore + n;
                    #pragma unroll
                    for (int e = 0; e < 4; e++) {
                        if (BIAS) vals[e] += bias[n + e];
                        if (RELU) vals[e] = fmaxf(vals[e], 0.f);
                    }
                    if (SPLIT) {
                        #pragma unroll
                        for (int e = 0; e < 4; e++) {
                            __nv_bfloat16 hi = __float2bfloat16(vals[e]);
                            oh[base + e] = hi;
                            ol[base + e] = __float2bfloat16(vals[e] - __bfloat162float(hi));
                        }
                    } else {
                        if (RESID) {
                            float4 rv = *(const float4*)&res[base];
                            vals[0] += rv.x; vals[1] += rv.y;
                            vals[2] += rv.z; vals[3] += rv.w;
                        }
                        float4 o;
                        o.x = vals[0]; o.y = vals[1]; o.z = vals[2]; o.w = vals[3];
                        *(float4*)&outf[base] = o;
                    }
                }
            }
            __syncthreads();   // eps dead before next tile's operand loads
        }
    }

    if (tid == 0) MBARRIER_INVAL(smem_base + GSM_MBAR);
    __syncthreads();
    if (wid == 0) TCGEN05_DEALLOC(tmem, 128);
#endif  // HAS_TCGEN05
}

// ================= fused causal attention (4-row batched, bcast-packed) =====
// smem: Kst[64][128] + Vs[128][68] + qs[8][64][4] + ps[8][128][4]
// Row-contiguous qw/pw layouts: QK reads q for 4 rows as ONE LDS.128
// broadcast per d; PV reads p for 4 rows as ONE LDS.128 broadcast per kk.
#define ATTN_SMEM ((64*128 + 128*68 + 8*4*64 + 8*4*128) * 4)   // 92160 B

__global__ __launch_bounds__(256)
void attn_kernel(const float* __restrict__ qkv,
                 __nv_bfloat16* __restrict__ oh, __nv_bfloat16* __restrict__ ol) {
    extern __shared__ float sm[];
    float* Kst = sm;                                 // [64][128] d-major
    float* Vs  = sm + 64 * 128;                      // [128][68]
    float* qs  = sm + 64 * 128 + 128 * 68;           // [8][64][4]
    float* ps  = qs + 8 * 64 * 4;                    // [8][128][4]

    const int b    = blockIdx.x >> 2;
    const int h    = blockIdx.x & 3;
    const int tid  = threadIdx.x;                    // 0..255
    const int lane = tid & 31;
    const int w    = tid >> 5;                       // 0..7

    const float* base_bt = qkv + (size_t)(b * Tt) * QKVN + h * HS;

    // Load K (transposed) and V: thread pair (row = tid>>1) covers one row.
    {
        const int row   = tid >> 1;
        const int dhalf = (tid & 1) * 32;
        const float* krow = base_bt + 256 + (size_t)row * QKVN + dhalf;
        const float* vrow = base_bt + 512 + (size_t)row * QKVN + dhalf;
        #pragma unroll
        for (int d4 = 0; d4 < 8; d4++) {
            int d = dhalf + d4 * 4;
            float4 kv = *(const float4*)(krow + d4 * 4);
            Kst[(d + 0) * 128 + row] = kv.x;
            Kst[(d + 1) * 128 + row] = kv.y;
            Kst[(d + 2) * 128 + row] = kv.z;
            Kst[(d + 3) * 128 + row] = kv.w;
            *(float4*)&Vs[row * 68 + d] = *(const float4*)(vrow + d4 * 4);
        }
    }
    __syncthreads();

    const float scale = 0.0625f;  // 256^-0.5
    float* qw = qs + w * 64 * 4;     // [d][4rows]
    float* pw = ps + w * 128 * 4;    // [kk][4rows]

    for (int batch = 0; batch < 4; batch++) {
        int qr[4];
        #pragma unroll
        for (int i = 0; i < 4; i++) qr[i] = (batch * 4 + i) * 8 + w;

        // stage 4 q rows: qw[d*4 + i] (16B stride across lanes, conflict-free)
        #pragma unroll
        for (int i = 0; i < 4; i++) {
            const float* qrow = base_bt + (size_t)qr[i] * QKVN;
            qw[lane * 4 + i]        = qrow[lane];
            qw[(lane + 32) * 4 + i] = qrow[lane + 32];
        }
        __syncwarp();

        // scores: s[i][e] for key kk = 4*lane + e
        float s[4][4];
        #pragma unroll
        for (int i = 0; i < 4; i++)
            #pragma unroll
            for (int e = 0; e < 4; e++) s[i][e] = 0.f;

        #pragma unroll 8
        for (int d = 0; d < 64; d++) {
            float4 kv = *(const float4*)&Kst[d * 128 + 4 * lane];
            float4 q4 = *(const float4*)&qw[d * 4];   // one broadcast: rows 0-3
            s[0][0] = fmaf(q4.x, kv.x, s[0][0]); s[0][1] = fmaf(q4.x, kv.y, s[0][1]);
            s[0][2] = fmaf(q4.x, kv.z, s[0][2]); s[0][3] = fmaf(q4.x, kv.w, s[0][3]);
            s[1][0] = fmaf(q4.y, kv.x, s[1][0]); s[1][1] = fmaf(q4.y, kv.y, s[1][1]);
            s[1][2] = fmaf(q4.y, kv.z, s[1][2]); s[1][3] = fmaf(q4.y, kv.w, s[1][3]);
            s[2][0] = fmaf(q4.z, kv.x, s[2][0]); s[2][1] = fmaf(q4.z, kv.y, s[2][1]);
            s[2][2] = fmaf(q4.z, kv.z, s[2][2]); s[2][3] = fmaf(q4.z, kv.w, s[2][3]);
            s[3][0] = fmaf(q4.w, kv.x, s[3][0]); s[3][1] = fmaf(q4.w, kv.y, s[3][1]);
            s[3][2] = fmaf(q4.w, kv.z, s[3][2]); s[3][3] = fmaf(q4.w, kv.w, s[3][3]);
        }

        // softmax per row; p[i][e] kept in regs, then packed stores [kk][4]
        float p[4][4];
        #pragma unroll
        for (int i = 0; i < 4; i++) {
            float e[4];
            float mx = -1e30f;
            #pragma unroll
            for (int ee = 0; ee < 4; ee++) {
                int kk = 4 * lane + ee;
                float sv = s[i][ee] * scale;
                s[i][ee] = sv;
                if (kk <= qr[i]) mx = fmaxf(mx, sv);
            }
            #pragma unroll
            for (int off = 16; off > 0; off >>= 1)
                mx = fmaxf(mx, __shfl_xor_sync(0xffffffffu, mx, off));
            float sum = 0.f;
            #pragma unroll
            for (int ee = 0; ee < 4; ee++) {
                int kk = 4 * lane + ee;
                e[ee] = (kk <= qr[i]) ? __expf(s[i][ee] - mx) : 0.f;
                sum += e[ee];
            }
            #pragma unroll
            for (int off = 16; off > 0; off >>= 1)
                sum += __shfl_xor_sync(0xffffffffu, sum, off);
            float rs = 1.0f / sum;
            #pragma unroll
            for (int ee = 0; ee < 4; ee++) p[i][ee] = e[ee] * rs;
        }
        // pw[(4*lane+e)*4 + i] : per lane a contiguous 64B block (4x STS.128)
        #pragma unroll
        for (int ee = 0; ee < 4; ee++) {
            float4 pv;
            pv.x = p[0][ee]; pv.y = p[1][ee]; pv.z = p[2][ee]; pv.w = p[3][ee];
            *(float4*)&pw[(4 * lane + ee) * 4] = pv;
        }
        __syncwarp();

        // PV: lane owns dims d0 = 2*lane, d1 = 2*lane+1
        float o[4][2];
        #pragma unroll
        for (int i = 0; i < 4; i++) { o[i][0] = 0.f; o[i][1] = 0.f; }
        const int kmax = qr[3];   // largest row in batch; masked p are 0
        #pragma unroll 4
        for (int kk = 0; kk <= kmax; kk++) {
            float2 v = *(const float2*)&Vs[kk * 68 + 2 * lane];
            float4 p4 = *(const float4*)&pw[kk * 4];  // one broadcast: rows 0-3
            o[0][0] = fmaf(p4.x, v.x, o[0][0]); o[0][1] = fmaf(p4.x, v.y, o[0][1]);
            o[1][0] = fmaf(p4.y, v.x, o[1][0]); o[1][1] = fmaf(p4.y, v.y, o[1][1]);
            o[2][0] = fmaf(p4.z, v.x, o[2][0]); o[2][1] = fmaf(p4.z, v.y, o[2][1]);
            o[3][0] = fmaf(p4.w, v.x, o[3][0]); o[3][1] = fmaf(p4.w, v.y, o[3][1]);
        }

        #pragma unroll
        for (int i = 0; i < 4; i++) {
            size_t obase = (size_t)(b * Tt + qr[i]) * Cc + h * HS + 2 * lane;
            __nv_bfloat16 h0 = __float2bfloat16(o[i][0]);
            __nv_bfloat16 h1 = __float2bfloat16(o[i][1]);
            oh[obase]     = h0;
            oh[obase + 1] = h1;
            ol[obase]     = __float2bfloat16(o[i][0] - __bfloat162float(h0));
            ol[obase + 1] = __float2bfloat16(o[i][1] - __bfloat162float(h1));
        }
        __syncwarp();   // qw/pw reused next batch
    }
}

// ================= launch ===================================================
extern "C" void kernel_launch(void* const* d_in, const int* in_sizes, int n_in,
                              void* d_out, int out_size) {
    const int*   idx   = (const int*)  d_in[0];
    const float* tok   = (const float*)d_in[1];
    const float* pos   = (const float*)d_in[2];
    const float* ln1g  = (const float*)d_in[3];
    const float* ln1b  = (const float*)d_in[4];
    const float* wq    = (const float*)d_in[5];
    const float* wk    = (const float*)d_in[6];
    const float* wv    = (const float*)d_in[7];
    const float* projw = (const float*)d_in[8];
    const float* projb = (const float*)d_in[9];
    const float* ln2g  = (const float*)d_in[10];
    const float* ln2b  = (const float*)d_in[11];
    const float* w1    = (const float*)d_in[12];
    const float* b1    = (const float*)d_in[13];
    const float* w2    = (const float*)d_in[14];
    const float* b2    = (const float*)d_in[15];
    const float* lnfg  = (const float*)d_in[16];
    const float* lnfb  = (const float*)d_in[17];
    const float* lmw   = (const float*)d_in[18];
    const float* lmb   = (const float*)d_in[19];
    float* out = (float*)d_out;

    float *x, *qkv;
    __nv_bfloat16 *hh, *hl, *ah, *al, *fh, *fl;
    __nv_bfloat16 *qkvTh, *qkvTl, *pTh, *pTl;
    __nv_bfloat16 *w1Th, *w1Tl, *w2Th, *w2Tl, *lmTh, *lmTl;
    cudaGetSymbolAddress((void**)&x,   g_x);
    cudaGetSymbolAddress((void**)&qkv, g_qkv);
    cudaGetSymbolAddress((void**)&hh, g_hh);  cudaGetSymbolAddress((void**)&hl, g_hl);
    cudaGetSymbolAddress((void**)&ah, g_ah);  cudaGetSymbolAddress((void**)&al, g_al);
    cudaGetSymbolAddress((void**)&fh, g_fh);  cudaGetSymbolAddress((void**)&fl, g_fl);
    cudaGetSymbolAddress((void**)&qkvTh, g_qkvT_h); cudaGetSymbolAddress((void**)&qkvTl, g_qkvT_l);
    cudaGetSymbolAddress((void**)&pTh,  g_pT_h);    cudaGetSymbolAddress((void**)&pTl,  g_pT_l);
    cudaGetSymbolAddress((void**)&w1Th, g_w1T_h);   cudaGetSymbolAddress((void**)&w1Tl, g_w1T_l);
    cudaGetSymbolAddress((void**)&w2Th, g_w2T_h);   cudaGetSymbolAddress((void**)&w2Tl, g_w2T_l);
    cudaGetSymbolAddress((void**)&lmTh, g_lmT_h);   cudaGetSymbolAddress((void**)&lmTl, g_lmT_l);

    cudaFuncSetAttribute(attn_kernel,
                         cudaFuncAttributeMaxDynamicSharedMemorySize, ATTN_SMEM);
    cudaFuncSetAttribute(tc_gemm<false,false,false,false>,
                         cudaFuncAttributeMaxDynamicSharedMemorySize, GSM_SIZE);
    cudaFuncSetAttribute(tc_gemm<true,false,true,false>,
                         cudaFuncAttributeMaxDynamicSharedMemorySize, GSM_SIZE);
    cudaFuncSetAttribute(tc_gemm<true,true,false,true>,
                         cudaFuncAttributeMaxDynamicSharedMemorySize, GSM_SIZE);
    cudaFuncSetAttribute(tc_gemm<true,false,false,false>,
                         cudaFuncAttributeMaxDynamicSharedMemorySize, GSM_SIZE);

    dim3 tb(32, 8);
    const dim3 gC(Cc / 128,   BT / 128);   // N=256
    const dim3 gQ(QKVN / 128, BT / 128);   // N=768
    const dim3 gF(DFF / 128,  BT / 128);   // N=1024
    const dim3 gV(VPAD / 512, BT / 128);   // LM head: 20 x 128, 4 N-tiles/CTA

    // Launch order: index 3 is the profiled launch -> attn_kernel.
    qkv_transpose<<<dim3(QKVN/32, Cc/32, Ll), tb>>>(wq, wk, wv, qkvTh, qkvTl);      // 0
    embed_ln_kernel<<<BT, 256>>>(idx, tok, pos, ln1g, ln1b, x, hh, hl);             // 1
    tc_gemm<false,false,false,false><<<gQ, 256, GSM_SIZE>>>(                        // 2
        hh, hl, qkvTh, qkvTl, nullptr, nullptr, qkv, nullptr, nullptr,
        QKVN, Cc, 1, QKVN);
    attn_kernel<<<Bb * Hh, 256, ATTN_SMEM>>>(qkv, ah, al);                          // 3 (PROFILED)
    transpose_split_g<<<dim3(Cc/32, Cc/32, Ll), tb>>>(projw, pTh, pTl, Cc, Cc,
                                                      (size_t)Cc*Cc, (size_t)Cc*Cc);
    transpose_split_g<<<dim3(DFF/32, Cc/32, Ll), tb>>>(w1, w1Th, w1Tl, Cc, DFF,
                                                       (size_t)Cc*DFF, (size_t)Cc*DFF);
    transpose_split_g<<<dim3(Cc/32, DFF/32, Ll), tb>>>(w2, w2Th, w2Tl, DFF, Cc,
                                                       (size_t)Cc*DFF, (size_t)Cc*DFF);
    transpose_split_g<<<dim3(VPAD/32, Cc/32, 1), tb>>>(lmw, lmTh, lmTl, Cc, Vv, 0, 0);

    for (int l = 0; l < Ll; l++) {
        size_t oQ = (size_t)l * QKVN * Cc;
        size_t o2 = (size_t)l * Cc * Cc;
        size_t oF = (size_t)l * Cc * DFF;

        if (l > 0) {
            ln_split_kernel<<<BT, 256>>>(x, ln1g + l*Cc, ln1b + l*Cc, hh, hl);
            tc_gemm<false,false,false,false><<<gQ, 256, GSM_SIZE>>>(
                hh, hl, qkvTh + oQ, qkvTl + oQ, nullptr, nullptr, qkv,
                nullptr, nullptr, QKVN, Cc, 1, QKVN);
            attn_kernel<<<Bb * Hh, 256, ATTN_SMEM>>>(qkv, ah, al);
        }

        tc_gemm<true,false,true,false><<<gC, 256, GSM_SIZE>>>(
            ah, al, pTh + o2, pTl + o2, projb + l*Cc, x, x, nullptr, nullptr,
            Cc, Cc, 1, Cc);

        ln_split_kernel<<<BT, 256>>>(x, ln2g + l*Cc, ln2b + l*Cc, hh, hl);

        tc_gemm<true,true,false,true><<<gF, 256, GSM_SIZE>>>(
            hh, hl, w1Th + oF, w1Tl + oF, b1 + l*DFF, nullptr, nullptr, fh, fl,
            DFF, Cc, 1, DFF);

        tc_gemm<true,false,true,false><<<gC, 256, GSM_SIZE>>>(
            fh, fl, w2Th + oF, w2Tl + oF, b2 + l*Cc, x, x, nullptr, nullptr,
            Cc, DFF, 1, Cc);
    }

    ln_split_kernel<<<BT, 256>>>(x, lnfg, lnfb, hh, hl);

    tc_gemm<true,false,false,false><<<gV, 256, GSM_SIZE>>>(
        hh, hl, lmTh, lmTl, lmb, nullptr, out, nullptr, nullptr,
        Vv, Cc, 4, VPAD);
}